// round 1
// baseline (speedup 1.0000x reference)
#include <cuda_runtime.h>

#define NN 50000
#define NG 64
#define DD 256
#define NE 800000
#define VOCAB 100000

// ---------------- scratch (device globals: no allocation allowed) -------------
__device__ float g_X[NN * DD];      // layer input (embeddings, then relu(layer1))
__device__ float g_HS[NN * DD];     // h * dis  (GEMM output, norm-folded)
__device__ float g_U[NN * DD];      // neighbor aggregation of HS
__device__ float g_DIS[NN];         // deg^{-1/2}
__device__ int   g_DEG[NN];
__device__ int   g_ROWPTR[NN + 1];
__device__ int   g_CPOS[NN];
__device__ int   g_CSRC[NE];
__device__ int   g_GSTART[NG + 1];

// ---------------- kernels ----------------------------------------------------

__global__ void k_zero_deg() {
    int n = blockIdx.x * blockDim.x + threadIdx.x;
    if (n < NN) g_DEG[n] = 0;
}

// x[n,d] = sum_t emb[seq[n,t], d]
__global__ void k_embed(const int* __restrict__ seq, const float* __restrict__ emb) {
    __shared__ int toks[16];
    int n = blockIdx.x;
    int d = threadIdx.x;
    if (d < 16) toks[d] = seq[n * 16 + d];
    __syncthreads();
    float acc = 0.f;
#pragma unroll
    for (int t = 0; t < 16; t++)
        acc += emb[toks[t] * DD + d];
    g_X[n * DD + d] = acc;
}

__global__ void k_count(const int* __restrict__ edge) {
    int e = blockIdx.x * blockDim.x + threadIdx.x;
    if (e < NE) atomicAdd(&g_DEG[edge[NE + e]], 1);
}

// single-block exclusive scan of g_DEG -> g_ROWPTR / g_CPOS
__global__ void k_scan() {
    __shared__ int sh[1024];
    int t = threadIdx.x;
    const int M = (NN + 1023) / 1024;  // 49
    int s0 = t * M;
    int s1 = s0 + M; if (s1 > NN) s1 = NN;
    int s = 0;
    for (int i = s0; i < s1; i++) s += g_DEG[i];
    sh[t] = s;
    __syncthreads();
    for (int off = 1; off < 1024; off <<= 1) {
        int v = (t >= off) ? sh[t - off] : 0;
        __syncthreads();
        sh[t] += v;
        __syncthreads();
    }
    int run = (t > 0) ? sh[t - 1] : 0;
    for (int i = s0; i < s1; i++) {
        g_ROWPTR[i] = run;
        g_CPOS[i] = run;
        run += g_DEG[i];
    }
    if (t == 0) g_ROWPTR[NN] = NE;
}

__global__ void k_fill(const int* __restrict__ edge) {
    int e = blockIdx.x * blockDim.x + threadIdx.x;
    if (e < NE) {
        int dst = edge[NE + e];
        int p = atomicAdd(&g_CPOS[dst], 1);
        g_CSRC[p] = edge[e];  // src
    }
}

__global__ void k_dis() {
    int n = blockIdx.x * blockDim.x + threadIdx.x;
    if (n < NN) g_DIS[n] = rsqrtf((float)g_DEG[n] + 1.0f);
}

// HS = (g_X @ W + bias) * dis[row]    (128x128x8 tiled SGEMM, 8x8 microtiles)
__global__ void __launch_bounds__(256) k_gemm(const float* __restrict__ B,
                                              const float* __restrict__ bias) {
    const int BM = 128, BN = 128, BK = 8, TM = 8, TN = 8;
    __shared__ float As[BK][BM];
    __shared__ float Bs[BK][BN];
    const float* A = g_X;
    int tid = threadIdx.x;
    int bC = blockIdx.x, bR = blockIdx.y;
    int tCol = tid & 15;         // 0..15
    int tRow = tid >> 4;         // 0..15
    int iRA = tid >> 1;          // 0..127
    int iCA = (tid & 1) * 4;     // 0 or 4
    int iRB = tid >> 5;          // 0..7
    int iCB = (tid & 31) * 4;    // 0..124
    int rowA = bR * BM + iRA;

    float acc[TM][TN];
#pragma unroll
    for (int i = 0; i < TM; i++)
#pragma unroll
        for (int j = 0; j < TN; j++) acc[i][j] = 0.f;

    for (int k0 = 0; k0 < DD; k0 += BK) {
        float4 a = (rowA < NN) ? *(const float4*)(A + rowA * DD + k0 + iCA)
                               : make_float4(0.f, 0.f, 0.f, 0.f);
        As[iCA + 0][iRA] = a.x;
        As[iCA + 1][iRA] = a.y;
        As[iCA + 2][iRA] = a.z;
        As[iCA + 3][iRA] = a.w;
        *(float4*)&Bs[iRB][iCB] = *(const float4*)(B + (k0 + iRB) * DD + bC * BN + iCB);
        __syncthreads();
#pragma unroll
        for (int k = 0; k < BK; k++) {
            float regM[TM], regN[TN];
#pragma unroll
            for (int i = 0; i < TM; i++) regM[i] = As[k][tRow * TM + i];
#pragma unroll
            for (int j = 0; j < TN; j++) regN[j] = Bs[k][tCol * TN + j];
#pragma unroll
            for (int i = 0; i < TM; i++)
#pragma unroll
                for (int j = 0; j < TN; j++)
                    acc[i][j] = fmaf(regM[i], regN[j], acc[i][j]);
        }
        __syncthreads();
    }
#pragma unroll
    for (int i = 0; i < TM; i++) {
        int row = bR * BM + tRow * TM + i;
        if (row >= NN) continue;
        float dis = g_DIS[row];
#pragma unroll
        for (int j = 0; j < TN; j += 4) {
            int col = bC * BN + tCol * TN + j;
            float4 o;
            o.x = (acc[i][j + 0] + bias[col + 0]) * dis;
            o.y = (acc[i][j + 1] + bias[col + 1]) * dis;
            o.z = (acc[i][j + 2] + bias[col + 2]) * dis;
            o.w = (acc[i][j + 3] + bias[col + 3]) * dis;
            *(float4*)(g_HS + row * DD + col) = o;
        }
    }
}

// U[n,d] = sum over incoming edges of HS[src,d]   (CSR gather, no atomics)
__global__ void k_agg() {
    __shared__ int srcs[256];
    int n = blockIdx.x;
    int d = threadIdx.x;
    int s = g_ROWPTR[n], e = g_ROWPTR[n + 1];
    float acc = 0.f;
    for (int base = s; base < e; base += 256) {
        int cnt = e - base; if (cnt > 256) cnt = 256;
        if (d < cnt) srcs[d] = g_CSRC[base + d];
        __syncthreads();
        for (int i = 0; i < cnt; i++)
            acc += g_HS[srcs[i] * DD + d];
        __syncthreads();
    }
    g_U[n * DD + d] = acc;
}

// X = relu(dis * (U + HS))   (layer-1 finalize -> next layer input)
__global__ void k_final1() {
    int n = blockIdx.x;
    int d = threadIdx.x;
    float v = g_DIS[n] * (g_U[n * DD + d] + g_HS[n * DD + d]);
    g_X[n * DD + d] = fmaxf(v, 0.f);
}

// graph boundaries via binary search on sorted batch ids
__global__ void k_gstart(const int* __restrict__ batch) {
    int t = threadIdx.x;
    if (t <= NG) {
        int lo = 0, hi = NN;
        while (lo < hi) {
            int mid = (lo + hi) >> 1;
            if (batch[mid] < t) lo = mid + 1; else hi = mid;
        }
        g_GSTART[t] = lo;
    }
}

// pooled[g,d] = sum over graph's nodes of relu(dis*(U+HS))   (fused L2 finalize)
__global__ void k_pool(float* __restrict__ out) {
    int g = blockIdx.x;
    int d = blockIdx.y * 128 + threadIdx.x;
    int s = g_GSTART[g], e = g_GSTART[g + 1];
    float acc = 0.f;
    for (int n = s; n < e; n++) {
        float v = g_DIS[n] * (g_U[n * DD + d] + g_HS[n * DD + d]);
        acc += fmaxf(v, 0.f);
    }
    out[g * DD + d] = acc;
}

// ---------------- launch ------------------------------------------------------

extern "C" void kernel_launch(void* const* d_in, const int* in_sizes, int n_in,
                              void* d_out, int out_size) {
    const int *seq = nullptr, *edge = nullptr, *batch = nullptr;
    const float *emb = nullptr, *W0 = nullptr, *b0 = nullptr, *W1 = nullptr, *b1 = nullptr;
    for (int i = 0; i < n_in; i++) {
        int s = in_sizes[i];
        if (s == NN * 16)            seq  = (const int*)d_in[i];
        else if (s == 2 * NE)        edge = (const int*)d_in[i];
        else if (s == NN)            batch = (const int*)d_in[i];
        else if (s == VOCAB * DD)    emb  = (const float*)d_in[i];
        else if (s == DD * DD) { if (!W0) W0 = (const float*)d_in[i]; else W1 = (const float*)d_in[i]; }
        else if (s == DD)      { if (!b0) b0 = (const float*)d_in[i]; else b1 = (const float*)d_in[i]; }
    }
    float* out = (float*)d_out;

    k_zero_deg<<<(NN + 255) / 256, 256>>>();
    k_embed<<<NN, 256>>>(seq, emb);
    k_count<<<(NE + 255) / 256, 256>>>(edge);
    k_scan<<<1, 1024>>>();
    k_fill<<<(NE + 255) / 256, 256>>>(edge);
    k_dis<<<(NN + 255) / 256, 256>>>();

    dim3 gg(DD / 128, (NN + 127) / 128);
    // layer 1
    k_gemm<<<gg, 256>>>(W0, b0);
    k_agg<<<NN, 256>>>();
    k_final1<<<NN, 256>>>();
    // layer 2
    k_gemm<<<gg, 256>>>(W1, b1);
    k_agg<<<NN, 256>>>();
    // pool (fuses layer-2 finalize + relu)
    k_gstart<<<1, 128>>>(batch);
    dim3 pg(NG, DD / 128);
    k_pool<<<pg, 128>>>(out);
}

// round 2
// speedup vs baseline: 1.5134x; 1.5134x over previous
#include <cuda_runtime.h>
#include <cstdint>

#define NN 50000
#define NG 64
#define DD 256
#define NE 800000
#define VOCAB 100000

// ---------------- scratch (device globals: no allocation allowed) -------------
__device__ float g_X[NN * DD];      // layer input (embeddings, then relu(layer1))
__device__ float g_HS[NN * DD];     // h * dis  (GEMM output, norm-folded)
__device__ float g_U[NN * DD];      // neighbor aggregation of HS
__device__ float g_DIS[NN];         // deg^{-1/2}
__device__ int   g_DEG[NN];
__device__ int   g_ROWPTR[NN + 1];
__device__ int   g_CPOS[NN];
__device__ int   g_CSRC[NE];
__device__ int   g_GSTART[NG + 1];
__device__ int   g_BSUM[256];

// ---------------- small kernels ----------------------------------------------

__global__ void k_zero_deg() {
    int n = blockIdx.x * blockDim.x + threadIdx.x;
    if (n < NN) g_DEG[n] = 0;
}

// x[n,d] = sum_t emb[seq[n,t], d]
__global__ void k_embed(const int* __restrict__ seq, const float* __restrict__ emb) {
    __shared__ int toks[16];
    int n = blockIdx.x;
    int d = threadIdx.x;
    if (d < 16) toks[d] = seq[n * 16 + d];
    __syncthreads();
    float acc = 0.f;
#pragma unroll
    for (int t = 0; t < 16; t++)
        acc += __ldg(emb + toks[t] * DD + d);
    g_X[n * DD + d] = acc;
}

__global__ void k_count(const int* __restrict__ edge) {
    int e = blockIdx.x * blockDim.x + threadIdx.x;
    if (e < NE) atomicAdd(&g_DEG[edge[NE + e]], 1);
}

// ---- parallel 3-pass exclusive scan of g_DEG ---------------------------------
__device__ __forceinline__ int block_scan_incl(int v, int t) {
    // 256-thread inclusive scan; returns inclusive prefix for this thread
    __shared__ int ws[8];
    int x = v;
#pragma unroll
    for (int o = 1; o < 32; o <<= 1) {
        int y = __shfl_up_sync(0xffffffffu, x, o);
        if ((t & 31) >= o) x += y;
    }
    if ((t & 31) == 31) ws[t >> 5] = x;
    __syncthreads();
    if (t < 8) {
        int s = ws[t];
#pragma unroll
        for (int o = 1; o < 8; o <<= 1) {
            int y = __shfl_up_sync(0xffu, s, o);
            if (t >= o) s += y;
        }
        ws[t] = s;
    }
    __syncthreads();
    int offs = (t >= 32) ? ws[(t >> 5) - 1] : 0;
    return x + offs;
}

__global__ void k_scan1() {   // 196 blocks x 256
    int t = threadIdx.x;
    int i = blockIdx.x * 256 + t;
    int v = (i < NN) ? g_DEG[i] : 0;
    int incl = block_scan_incl(v, t);
    if (i < NN) g_ROWPTR[i] = incl - v;      // local exclusive
    if (t == 255) g_BSUM[blockIdx.x] = incl; // block total
}

__global__ void k_scan2() {   // 1 block x 256
    int t = threadIdx.x;
    int v = (t < 196) ? g_BSUM[t] : 0;       // read before first sync -> safe
    int incl = block_scan_incl(v, t);
    if (t < 196) g_BSUM[t] = incl - v;       // exclusive block offsets
}

__global__ void k_scan3() {   // 196 blocks x 256  (+ fused dis)
    int t = threadIdx.x;
    int i = blockIdx.x * 256 + t;
    if (i < NN) {
        int rp = g_ROWPTR[i] + g_BSUM[blockIdx.x];
        g_ROWPTR[i] = rp;
        g_CPOS[i] = rp;
        g_DIS[i] = rsqrtf((float)g_DEG[i] + 1.0f);
    }
    if (i == 0) g_ROWPTR[NN] = NE;
}

__global__ void k_fill(const int* __restrict__ edge) {
    int e = blockIdx.x * blockDim.x + threadIdx.x;
    if (e < NE) {
        int dst = edge[NE + e];
        int p = atomicAdd(&g_CPOS[dst], 1);
        g_CSRC[p] = edge[e];  // src
    }
}

// ---------------- TF32 tensor-core GEMM ---------------------------------------
// HS = (g_X @ W + bias) * dis[row]
// 128x128 block tile, BK=16, 8 warps in 2x4 grid, warp tile 64x32,
// mma.sync m16n8k8 tf32 (fp32 accumulate).

__device__ __forceinline__ uint32_t f2tf32(float f) {
    uint32_t u;
    asm volatile("cvt.rna.tf32.f32 %0, %1;\n" : "=r"(u) : "f"(f));
    return u;
}

#define MMA_TF32(d, a, b)                                                      \
    asm volatile(                                                              \
        "mma.sync.aligned.m16n8k8.row.col.f32.tf32.tf32.f32 "                  \
        "{%0,%1,%2,%3},{%4,%5,%6,%7},{%8,%9},{%0,%1,%2,%3};"                   \
        : "+f"(d[0]), "+f"(d[1]), "+f"(d[2]), "+f"(d[3])                       \
        : "r"(a[0]), "r"(a[1]), "r"(a[2]), "r"(a[3]), "r"(b[0]), "r"(b[1]))

__global__ void __launch_bounds__(256) k_gemm(const float* __restrict__ W,
                                              const float* __restrict__ bias) {
    const int ASTR = 20;    // As row stride (floats): [m][k], pad -> conflict-free
    const int BSTR = 136;   // Bs row stride (floats): [k][n], pad -> conflict-free
    __shared__ uint32_t As[128 * ASTR];
    __shared__ uint32_t Bs[16 * BSTR];

    int tid = threadIdx.x;
    int warp = tid >> 5, lane = tid & 31;
    int r = lane >> 2, c = lane & 3;       // groupID, threadID_in_group
    int wm = (warp >> 2) * 64;             // warp row offset (0 or 64)
    int wn = (warp & 3) * 32;              // warp col offset (0..96)
    int bR = blockIdx.y, bC = blockIdx.x;

    float acc[4][4][4];
#pragma unroll
    for (int i = 0; i < 4; i++)
#pragma unroll
        for (int j = 0; j < 4; j++)
#pragma unroll
            for (int q = 0; q < 4; q++) acc[i][j][q] = 0.f;

    for (int k0 = 0; k0 < DD; k0 += 16) {
        // load A tile (128x16) transposed-free into [m][k]
#pragma unroll
        for (int i = 0; i < 2; i++) {
            int idx = tid + i * 256;
            int m = idx >> 2;
            int kk = (idx & 3) * 4;
            int grow = bR * 128 + m;
            float4 v = (grow < NN)
                           ? *(const float4*)(g_X + grow * DD + k0 + kk)
                           : make_float4(0.f, 0.f, 0.f, 0.f);
            As[m * ASTR + kk + 0] = f2tf32(v.x);
            As[m * ASTR + kk + 1] = f2tf32(v.y);
            As[m * ASTR + kk + 2] = f2tf32(v.z);
            As[m * ASTR + kk + 3] = f2tf32(v.w);
        }
        // load B tile (16x128) into [k][n]
#pragma unroll
        for (int i = 0; i < 2; i++) {
            int idx = tid + i * 256;
            int kr = idx >> 5;
            int c4 = (idx & 31) * 4;
            float4 v = *(const float4*)(W + (k0 + kr) * DD + bC * 128 + c4);
            Bs[kr * BSTR + c4 + 0] = f2tf32(v.x);
            Bs[kr * BSTR + c4 + 1] = f2tf32(v.y);
            Bs[kr * BSTR + c4 + 2] = f2tf32(v.z);
            Bs[kr * BSTR + c4 + 3] = f2tf32(v.w);
        }
        __syncthreads();

#pragma unroll
        for (int ks = 0; ks < 16; ks += 8) {
            uint32_t a[4][4], b[4][2];
#pragma unroll
            for (int ti = 0; ti < 4; ti++) {
                int m0 = wm + ti * 16;
                a[ti][0] = As[(m0 + r) * ASTR + ks + c];
                a[ti][1] = As[(m0 + r + 8) * ASTR + ks + c];
                a[ti][2] = As[(m0 + r) * ASTR + ks + c + 4];
                a[ti][3] = As[(m0 + r + 8) * ASTR + ks + c + 4];
            }
#pragma unroll
            for (int tj = 0; tj < 4; tj++) {
                int n0 = wn + tj * 8 + r;
                b[tj][0] = Bs[(ks + c) * BSTR + n0];
                b[tj][1] = Bs[(ks + c + 4) * BSTR + n0];
            }
#pragma unroll
            for (int ti = 0; ti < 4; ti++)
#pragma unroll
                for (int tj = 0; tj < 4; tj++) MMA_TF32(acc[ti][tj], a[ti], b[tj]);
        }
        __syncthreads();
    }

    // epilogue: HS = (acc + bias) * dis[row]
#pragma unroll
    for (int ti = 0; ti < 4; ti++) {
        int row0 = bR * 128 + wm + ti * 16 + r;
        int row1 = row0 + 8;
        float dis0 = (row0 < NN) ? g_DIS[row0] : 0.f;
        float dis1 = (row1 < NN) ? g_DIS[row1] : 0.f;
#pragma unroll
        for (int tj = 0; tj < 4; tj++) {
            int col = bC * 128 + wn + tj * 8 + 2 * c;
            float bx = __ldg(bias + col), by = __ldg(bias + col + 1);
            if (row0 < NN) {
                float2 o = make_float2((acc[ti][tj][0] + bx) * dis0,
                                       (acc[ti][tj][1] + by) * dis0);
                *(float2*)(g_HS + row0 * DD + col) = o;
            }
            if (row1 < NN) {
                float2 o = make_float2((acc[ti][tj][2] + bx) * dis1,
                                       (acc[ti][tj][3] + by) * dis1);
                *(float2*)(g_HS + row1 * DD + col) = o;
            }
        }
    }
}

// ---------------- aggregation (CSR gather, no atomics) -------------------------
// layer1: X = relu(dis * (U + HS))  fused; layer2: write U only.
template <int FUSE_RELU>
__global__ void k_agg() {
    __shared__ int srcs[256];
    int n = blockIdx.x;
    int d = threadIdx.x;
    int s = g_ROWPTR[n], e = g_ROWPTR[n + 1];
    float acc = 0.f;
    for (int base = s; base < e; base += 256) {
        int cnt = e - base; if (cnt > 256) cnt = 256;
        if (d < cnt) srcs[d] = g_CSRC[base + d];
        __syncthreads();
        for (int i = 0; i < cnt; i++)
            acc += g_HS[srcs[i] * DD + d];
        __syncthreads();
    }
    if (FUSE_RELU) {
        float v = g_DIS[n] * (acc + g_HS[n * DD + d]);
        g_X[n * DD + d] = fmaxf(v, 0.f);
    } else {
        g_U[n * DD + d] = acc;
    }
}

// graph boundaries via binary search on sorted batch ids
__global__ void k_gstart(const int* __restrict__ batch) {
    int t = threadIdx.x;
    if (t <= NG) {
        int lo = 0, hi = NN;
        while (lo < hi) {
            int mid = (lo + hi) >> 1;
            if (batch[mid] < t) lo = mid + 1; else hi = mid;
        }
        g_GSTART[t] = lo;
    }
}

// pooled[g,d] = sum over graph's nodes of relu(dis*(U+HS))  (fused L2 finalize)
__global__ void k_pool(float* __restrict__ out) {
    int g = blockIdx.x;
    int d = blockIdx.y * 128 + threadIdx.x;
    int s = g_GSTART[g], e = g_GSTART[g + 1];
    float acc = 0.f;
    for (int n = s; n < e; n++) {
        float v = g_DIS[n] * (g_U[n * DD + d] + g_HS[n * DD + d]);
        acc += fmaxf(v, 0.f);
    }
    out[g * DD + d] = acc;
}

// ---------------- launch ------------------------------------------------------

extern "C" void kernel_launch(void* const* d_in, const int* in_sizes, int n_in,
                              void* d_out, int out_size) {
    const int *seq = nullptr, *edge = nullptr, *batch = nullptr;
    const float *emb = nullptr, *W0 = nullptr, *b0 = nullptr, *W1 = nullptr, *b1 = nullptr;
    for (int i = 0; i < n_in; i++) {
        int s = in_sizes[i];
        if (s == NN * 16)            seq  = (const int*)d_in[i];
        else if (s == 2 * NE)        edge = (const int*)d_in[i];
        else if (s == NN)            batch = (const int*)d_in[i];
        else if (s == VOCAB * DD)    emb  = (const float*)d_in[i];
        else if (s == DD * DD) { if (!W0) W0 = (const float*)d_in[i]; else W1 = (const float*)d_in[i]; }
        else if (s == DD)      { if (!b0) b0 = (const float*)d_in[i]; else b1 = (const float*)d_in[i]; }
    }
    float* out = (float*)d_out;

    const int SB = 196;  // ceil(NN/256)

    k_zero_deg<<<(NN + 255) / 256, 256>>>();
    k_embed<<<NN, 256>>>(seq, emb);
    k_count<<<(NE + 255) / 256, 256>>>(edge);
    k_scan1<<<SB, 256>>>();
    k_scan2<<<1, 256>>>();
    k_scan3<<<SB, 256>>>();
    k_fill<<<(NE + 255) / 256, 256>>>(edge);
    k_gstart<<<1, 128>>>(batch);

    dim3 gg(DD / 128, (NN + 127) / 128);
    // layer 1
    k_gemm<<<gg, 256>>>(W0, b0);
    k_agg<1><<<NN, 256>>>();
    // layer 2
    k_gemm<<<gg, 256>>>(W1, b1);
    k_agg<0><<<NN, 256>>>();
    // pool (fuses layer-2 finalize + relu)
    dim3 pg(NG, DD / 128);
    k_pool<<<pg, 128>>>(out);
}

// round 3
// speedup vs baseline: 2.4071x; 1.5905x over previous
#include <cuda_runtime.h>
#include <cstdint>

#define NN 50000
#define NG 64
#define DD 256
#define NE 800000
#define VOCAB 100000

// ---------------- scratch (device globals: no allocation allowed) -------------
__device__ float g_X[NN * DD];      // layer input (embeddings, then relu(layer1))
__device__ float g_HS[NN * DD];     // h * dis  (GEMM output, norm-folded)
__device__ float g_U[NN * DD];      // layer2: relu(dis*(agg+HS))  (final node feats)
__device__ float g_DIS[NN];         // deg^{-1/2}
__device__ int   g_DEG[NN];
__device__ int   g_ROWPTR[NN + 1];
__device__ int   g_CPOS[NN];
__device__ int   g_CSRC[NE];
__device__ int   g_GSTART[NG + 1];
__device__ int   g_BSUM[256];
__device__ float g_PART[8 * NG * DD];

// ---------------- small kernels ----------------------------------------------

__global__ void k_zero_deg() {
    int n = blockIdx.x * blockDim.x + threadIdx.x;
    if (n < NN) g_DEG[n] = 0;
}

// x[n,:] = sum_t emb[seq[n,t],:]   — warp per node, float4 lanes
__global__ void __launch_bounds__(256) k_embed(const int* __restrict__ seq,
                                               const float* __restrict__ emb) {
    int w = (blockIdx.x * blockDim.x + threadIdx.x) >> 5;
    int lane = threadIdx.x & 31;
    if (w >= NN) return;
    int tok = (lane < 16) ? seq[w * 16 + lane] : 0;
    const float4* E4 = (const float4*)emb;
    float4 a0 = make_float4(0.f, 0.f, 0.f, 0.f);
    float4 a1 = make_float4(0.f, 0.f, 0.f, 0.f);
#pragma unroll
    for (int t = 0; t < 16; t++) {
        int tk = __shfl_sync(0xffffffffu, tok, t);
        const float4* row = E4 + tk * 64;
        float4 v0 = __ldg(row + lane);
        float4 v1 = __ldg(row + lane + 32);
        a0.x += v0.x; a0.y += v0.y; a0.z += v0.z; a0.w += v0.w;
        a1.x += v1.x; a1.y += v1.y; a1.z += v1.z; a1.w += v1.w;
    }
    float4* X4 = (float4*)g_X;
    X4[w * 64 + lane] = a0;
    X4[w * 64 + lane + 32] = a1;
}

__global__ void k_count(const int* __restrict__ edge) {
    int e = blockIdx.x * blockDim.x + threadIdx.x;
    if (e < NE) atomicAdd(&g_DEG[edge[NE + e]], 1);
}

// ---- parallel 3-pass exclusive scan of g_DEG ---------------------------------
__device__ __forceinline__ int block_scan_incl(int v, int t) {
    __shared__ int ws[8];
    int x = v;
#pragma unroll
    for (int o = 1; o < 32; o <<= 1) {
        int y = __shfl_up_sync(0xffffffffu, x, o);
        if ((t & 31) >= o) x += y;
    }
    if ((t & 31) == 31) ws[t >> 5] = x;
    __syncthreads();
    if (t < 8) {
        int s = ws[t];
#pragma unroll
        for (int o = 1; o < 8; o <<= 1) {
            int y = __shfl_up_sync(0xffu, s, o);
            if (t >= o) s += y;
        }
        ws[t] = s;
    }
    __syncthreads();
    int offs = (t >= 32) ? ws[(t >> 5) - 1] : 0;
    return x + offs;
}

__global__ void k_scan1() {
    int t = threadIdx.x;
    int i = blockIdx.x * 256 + t;
    int v = (i < NN) ? g_DEG[i] : 0;
    int incl = block_scan_incl(v, t);
    if (i < NN) g_ROWPTR[i] = incl - v;
    if (t == 255) g_BSUM[blockIdx.x] = incl;
}

__global__ void k_scan2() {
    int t = threadIdx.x;
    int v = (t < 196) ? g_BSUM[t] : 0;
    int incl = block_scan_incl(v, t);
    if (t < 196) g_BSUM[t] = incl - v;
}

__global__ void k_scan3() {
    int t = threadIdx.x;
    int i = blockIdx.x * 256 + t;
    if (i < NN) {
        int rp = g_ROWPTR[i] + g_BSUM[blockIdx.x];
        g_ROWPTR[i] = rp;
        g_CPOS[i] = rp;
        g_DIS[i] = rsqrtf((float)g_DEG[i] + 1.0f);
    }
    if (i == 0) g_ROWPTR[NN] = NE;
}

__global__ void k_fill(const int* __restrict__ edge) {
    int e = blockIdx.x * blockDim.x + threadIdx.x;
    if (e < NE) {
        int dst = edge[NE + e];
        int p = atomicAdd(&g_CPOS[dst], 1);
        g_CSRC[p] = edge[e];
    }
}

// ---------------- TF32 tensor-core GEMM ---------------------------------------
__device__ __forceinline__ uint32_t f2tf32(float f) {
    uint32_t u;
    asm volatile("cvt.rna.tf32.f32 %0, %1;\n" : "=r"(u) : "f"(f));
    return u;
}

#define MMA_TF32(d, a, b)                                                      \
    asm volatile(                                                              \
        "mma.sync.aligned.m16n8k8.row.col.f32.tf32.tf32.f32 "                  \
        "{%0,%1,%2,%3},{%4,%5,%6,%7},{%8,%9},{%0,%1,%2,%3};"                   \
        : "+f"(d[0]), "+f"(d[1]), "+f"(d[2]), "+f"(d[3])                       \
        : "r"(a[0]), "r"(a[1]), "r"(a[2]), "r"(a[3]), "r"(b[0]), "r"(b[1]))

__global__ void __launch_bounds__(256) k_gemm(const float* __restrict__ W,
                                              const float* __restrict__ bias) {
    const int ASTR = 20;
    const int BSTR = 136;
    __shared__ uint32_t As[128 * ASTR];
    __shared__ uint32_t Bs[16 * BSTR];

    int tid = threadIdx.x;
    int warp = tid >> 5, lane = tid & 31;
    int r = lane >> 2, c = lane & 3;
    int wm = (warp >> 2) * 64;
    int wn = (warp & 3) * 32;
    int bR = blockIdx.y, bC = blockIdx.x;

    float acc[4][4][4];
#pragma unroll
    for (int i = 0; i < 4; i++)
#pragma unroll
        for (int j = 0; j < 4; j++)
#pragma unroll
            for (int q = 0; q < 4; q++) acc[i][j][q] = 0.f;

    for (int k0 = 0; k0 < DD; k0 += 16) {
#pragma unroll
        for (int i = 0; i < 2; i++) {
            int idx = tid + i * 256;
            int m = idx >> 2;
            int kk = (idx & 3) * 4;
            int grow = bR * 128 + m;
            float4 v = (grow < NN)
                           ? *(const float4*)(g_X + grow * DD + k0 + kk)
                           : make_float4(0.f, 0.f, 0.f, 0.f);
            As[m * ASTR + kk + 0] = f2tf32(v.x);
            As[m * ASTR + kk + 1] = f2tf32(v.y);
            As[m * ASTR + kk + 2] = f2tf32(v.z);
            As[m * ASTR + kk + 3] = f2tf32(v.w);
        }
#pragma unroll
        for (int i = 0; i < 2; i++) {
            int idx = tid + i * 256;
            int kr = idx >> 5;
            int c4 = (idx & 31) * 4;
            float4 v = *(const float4*)(W + (k0 + kr) * DD + bC * 128 + c4);
            Bs[kr * BSTR + c4 + 0] = f2tf32(v.x);
            Bs[kr * BSTR + c4 + 1] = f2tf32(v.y);
            Bs[kr * BSTR + c4 + 2] = f2tf32(v.z);
            Bs[kr * BSTR + c4 + 3] = f2tf32(v.w);
        }
        __syncthreads();

#pragma unroll
        for (int ks = 0; ks < 16; ks += 8) {
            uint32_t a[4][4], b[4][2];
#pragma unroll
            for (int ti = 0; ti < 4; ti++) {
                int m0 = wm + ti * 16;
                a[ti][0] = As[(m0 + r) * ASTR + ks + c];
                a[ti][1] = As[(m0 + r + 8) * ASTR + ks + c];
                a[ti][2] = As[(m0 + r) * ASTR + ks + c + 4];
                a[ti][3] = As[(m0 + r + 8) * ASTR + ks + c + 4];
            }
#pragma unroll
            for (int tj = 0; tj < 4; tj++) {
                int n0 = wn + tj * 8 + r;
                b[tj][0] = Bs[(ks + c) * BSTR + n0];
                b[tj][1] = Bs[(ks + c + 4) * BSTR + n0];
            }
#pragma unroll
            for (int ti = 0; ti < 4; ti++)
#pragma unroll
                for (int tj = 0; tj < 4; tj++) MMA_TF32(acc[ti][tj], a[ti], b[tj]);
        }
        __syncthreads();
    }

#pragma unroll
    for (int ti = 0; ti < 4; ti++) {
        int row0 = bR * 128 + wm + ti * 16 + r;
        int row1 = row0 + 8;
        float dis0 = (row0 < NN) ? g_DIS[row0] : 0.f;
        float dis1 = (row1 < NN) ? g_DIS[row1] : 0.f;
#pragma unroll
        for (int tj = 0; tj < 4; tj++) {
            int col = bC * 128 + wn + tj * 8 + 2 * c;
            float bx = __ldg(bias + col), by = __ldg(bias + col + 1);
            if (row0 < NN) {
                float2 o = make_float2((acc[ti][tj][0] + bx) * dis0,
                                       (acc[ti][tj][1] + by) * dis0);
                *(float2*)(g_HS + row0 * DD + col) = o;
            }
            if (row1 < NN) {
                float2 o = make_float2((acc[ti][tj][2] + bx) * dis1,
                                       (acc[ti][tj][3] + by) * dis1);
                *(float2*)(g_HS + row1 * DD + col) = o;
            }
        }
    }
}

// ---------------- aggregation: warp per node, float4 gather --------------------
// LAYER1: g_X = relu(dis*(sum + HS))   LAYER2: g_U = relu(dis*(sum + HS))
template <int LAYER1>
__global__ void __launch_bounds__(256) k_agg() {
    int w = (blockIdx.x * blockDim.x + threadIdx.x) >> 5;
    int lane = threadIdx.x & 31;
    if (w >= NN) return;
    int s = g_ROWPTR[w], e = g_ROWPTR[w + 1];
    const float4* HS4 = (const float4*)g_HS;
    float4 a0 = make_float4(0.f, 0.f, 0.f, 0.f);
    float4 a1 = make_float4(0.f, 0.f, 0.f, 0.f);
    for (int base = s; base < e; base += 32) {
        int cnt = e - base; if (cnt > 32) cnt = 32;
        int mysrc = (lane < cnt) ? g_CSRC[base + lane] : 0;
#pragma unroll 4
        for (int i = 0; i < cnt; i++) {
            int src = __shfl_sync(0xffffffffu, mysrc, i);
            const float4* row = HS4 + src * 64;
            float4 v0 = __ldg(row + lane);
            float4 v1 = __ldg(row + lane + 32);
            a0.x += v0.x; a0.y += v0.y; a0.z += v0.z; a0.w += v0.w;
            a1.x += v1.x; a1.y += v1.y; a1.z += v1.z; a1.w += v1.w;
        }
    }
    // self-loop + finalize
    const float4* self = HS4 + w * 64;
    float4 s0 = __ldg(self + lane);
    float4 s1 = __ldg(self + lane + 32);
    float dis = g_DIS[w];
    float4 o0, o1;
    o0.x = fmaxf(dis * (a0.x + s0.x), 0.f);
    o0.y = fmaxf(dis * (a0.y + s0.y), 0.f);
    o0.z = fmaxf(dis * (a0.z + s0.z), 0.f);
    o0.w = fmaxf(dis * (a0.w + s0.w), 0.f);
    o1.x = fmaxf(dis * (a1.x + s1.x), 0.f);
    o1.y = fmaxf(dis * (a1.y + s1.y), 0.f);
    o1.z = fmaxf(dis * (a1.z + s1.z), 0.f);
    o1.w = fmaxf(dis * (a1.w + s1.w), 0.f);
    float4* OUT4 = LAYER1 ? (float4*)g_X : (float4*)g_U;
    OUT4[w * 64 + lane] = o0;
    OUT4[w * 64 + lane + 32] = o1;
}

// graph boundaries via binary search on sorted batch ids
__global__ void k_gstart(const int* __restrict__ batch) {
    int t = threadIdx.x;
    if (t <= NG) {
        int lo = 0, hi = NN;
        while (lo < hi) {
            int mid = (lo + hi) >> 1;
            if (batch[mid] < t) lo = mid + 1; else hi = mid;
        }
        g_GSTART[t] = lo;
    }
}

// pool pass 1: 8 node-chunks per graph -> partial sums (float4 lanes)
__global__ void k_pool1() {
    int g = blockIdx.x, ch = blockIdx.y;
    int lane = threadIdx.x;  // 64 threads, float4 each
    int s = g_GSTART[g], e = g_GSTART[g + 1];
    int len = e - s;
    int c0 = s + (int)(((long long)len * ch) >> 3);
    int c1 = s + (int)(((long long)len * (ch + 1)) >> 3);
    const float4* U4 = (const float4*)g_U;
    float4 acc = make_float4(0.f, 0.f, 0.f, 0.f);
    for (int n = c0; n < c1; n++) {
        float4 v = __ldg(U4 + n * 64 + lane);
        acc.x += v.x; acc.y += v.y; acc.z += v.z; acc.w += v.w;
    }
    ((float4*)g_PART)[(ch * NG + g) * 64 + lane] = acc;
}

// pool pass 2: reduce the 8 partials
__global__ void k_pool2(float* __restrict__ out) {
    int g = blockIdx.x;
    int lane = threadIdx.x;  // 64
    const float4* P4 = (const float4*)g_PART;
    float4 acc = make_float4(0.f, 0.f, 0.f, 0.f);
#pragma unroll
    for (int ch = 0; ch < 8; ch++) {
        float4 v = P4[(ch * NG + g) * 64 + lane];
        acc.x += v.x; acc.y += v.y; acc.z += v.z; acc.w += v.w;
    }
    ((float4*)out)[g * 64 + lane] = acc;
}

// ---------------- launch ------------------------------------------------------

extern "C" void kernel_launch(void* const* d_in, const int* in_sizes, int n_in,
                              void* d_out, int out_size) {
    const int *seq = nullptr, *edge = nullptr, *batch = nullptr;
    const float *emb = nullptr, *W0 = nullptr, *b0 = nullptr, *W1 = nullptr, *b1 = nullptr;
    for (int i = 0; i < n_in; i++) {
        int s = in_sizes[i];
        if (s == NN * 16)            seq  = (const int*)d_in[i];
        else if (s == 2 * NE)        edge = (const int*)d_in[i];
        else if (s == NN)            batch = (const int*)d_in[i];
        else if (s == VOCAB * DD)    emb  = (const float*)d_in[i];
        else if (s == DD * DD) { if (!W0) W0 = (const float*)d_in[i]; else W1 = (const float*)d_in[i]; }
        else if (s == DD)      { if (!b0) b0 = (const float*)d_in[i]; else b1 = (const float*)d_in[i]; }
    }
    float* out = (float*)d_out;

    const int SB = 196;          // ceil(NN/256)
    const int WB = (NN + 7) / 8; // warp-per-node blocks (8 warps each)

    k_zero_deg<<<(NN + 255) / 256, 256>>>();
    k_embed<<<WB, 256>>>(seq, emb);
    k_count<<<(NE + 255) / 256, 256>>>(edge);
    k_scan1<<<SB, 256>>>();
    k_scan2<<<1, 256>>>();
    k_scan3<<<SB, 256>>>();
    k_fill<<<(NE + 255) / 256, 256>>>(edge);
    k_gstart<<<1, 128>>>(batch);

    dim3 gg(DD / 128, (NN + 127) / 128);
    // layer 1
    k_gemm<<<gg, 256>>>(W0, b0);
    k_agg<1><<<WB, 256>>>();
    // layer 2
    k_gemm<<<gg, 256>>>(W1, b1);
    k_agg<0><<<WB, 256>>>();
    // pool
    dim3 pg(NG, 8);
    k_pool1<<<pg, 64>>>();
    k_pool2<<<NG, 64>>>(out);
}

// round 4
// speedup vs baseline: 2.5919x; 1.0768x over previous
#include <cuda_runtime.h>
#include <cuda_fp16.h>
#include <cstdint>

#define NN 50000
#define NG 64
#define DD 256
#define NE 800000
#define VOCAB 100000

// ---------------- scratch (device globals: no allocation allowed) -------------
__device__ float  g_X[NN * DD];     // layer input (embeddings, then relu(layer1))
__device__ __half g_HSH[NN * DD];   // h * dis (GEMM output, norm-folded), fp16
__device__ float  g_U[NN * DD];     // layer2 final node feats
__device__ float  g_DIS[NN];        // deg^{-1/2}
__device__ int    g_DEG[NN];
__device__ int    g_ROWPTR[NN + 1];
__device__ int    g_CPOS[NN];
__device__ int    g_CSRC[NE];
__device__ int    g_GSTART[NG + 1];
__device__ int    g_BSUM[256];
__device__ float  g_PART[8 * NG * DD];

// ---------------- small kernels ----------------------------------------------

__global__ void k_zero_deg() {
    int n = blockIdx.x * blockDim.x + threadIdx.x;
    if (n < NN) g_DEG[n] = 0;
}

// x[n,:] = sum_t emb[seq[n,t],:]   — warp per node, float4 lanes
__global__ void __launch_bounds__(256) k_embed(const int* __restrict__ seq,
                                               const float* __restrict__ emb) {
    int w = (blockIdx.x * blockDim.x + threadIdx.x) >> 5;
    int lane = threadIdx.x & 31;
    if (w >= NN) return;
    int tok = (lane < 16) ? seq[w * 16 + lane] : 0;
    const float4* E4 = (const float4*)emb;
    float4 a0 = make_float4(0.f, 0.f, 0.f, 0.f);
    float4 a1 = make_float4(0.f, 0.f, 0.f, 0.f);
#pragma unroll
    for (int t = 0; t < 16; t++) {
        int tk = __shfl_sync(0xffffffffu, tok, t);
        const float4* row = E4 + tk * 64;
        float4 v0 = __ldg(row + lane);
        float4 v1 = __ldg(row + lane + 32);
        a0.x += v0.x; a0.y += v0.y; a0.z += v0.z; a0.w += v0.w;
        a1.x += v1.x; a1.y += v1.y; a1.z += v1.z; a1.w += v1.w;
    }
    float4* X4 = (float4*)g_X;
    X4[w * 64 + lane] = a0;
    X4[w * 64 + lane + 32] = a1;
}

__global__ void k_count(const int* __restrict__ edge) {
    int e = blockIdx.x * blockDim.x + threadIdx.x;
    if (e < NE) atomicAdd(&g_DEG[edge[NE + e]], 1);
}

// ---- parallel 3-pass exclusive scan of g_DEG ---------------------------------
__device__ __forceinline__ int block_scan_incl(int v, int t) {
    __shared__ int ws[8];
    int x = v;
#pragma unroll
    for (int o = 1; o < 32; o <<= 1) {
        int y = __shfl_up_sync(0xffffffffu, x, o);
        if ((t & 31) >= o) x += y;
    }
    if ((t & 31) == 31) ws[t >> 5] = x;
    __syncthreads();
    if (t < 8) {
        int s = ws[t];
#pragma unroll
        for (int o = 1; o < 8; o <<= 1) {
            int y = __shfl_up_sync(0xffu, s, o);
            if (t >= o) s += y;
        }
        ws[t] = s;
    }
    __syncthreads();
    int offs = (t >= 32) ? ws[(t >> 5) - 1] : 0;
    return x + offs;
}

__global__ void k_scan1() {
    int t = threadIdx.x;
    int i = blockIdx.x * 256 + t;
    int v = (i < NN) ? g_DEG[i] : 0;
    int incl = block_scan_incl(v, t);
    if (i < NN) g_ROWPTR[i] = incl - v;
    if (t == 255) g_BSUM[blockIdx.x] = incl;
}

__global__ void k_scan2() {
    int t = threadIdx.x;
    int v = (t < 196) ? g_BSUM[t] : 0;
    int incl = block_scan_incl(v, t);
    if (t < 196) g_BSUM[t] = incl - v;
}

__global__ void k_scan3() {
    int t = threadIdx.x;
    int i = blockIdx.x * 256 + t;
    if (i < NN) {
        int rp = g_ROWPTR[i] + g_BSUM[blockIdx.x];
        g_ROWPTR[i] = rp;
        g_CPOS[i] = rp;
        g_DIS[i] = rsqrtf((float)g_DEG[i] + 1.0f);
    }
    if (i == 0) g_ROWPTR[NN] = NE;
}

__global__ void k_fill(const int* __restrict__ edge) {
    int e = blockIdx.x * blockDim.x + threadIdx.x;
    if (e < NE) {
        int dst = edge[NE + e];
        int p = atomicAdd(&g_CPOS[dst], 1);
        g_CSRC[p] = edge[e];
    }
}

// ---------------- TF32 tensor-core GEMM ---------------------------------------
__device__ __forceinline__ uint32_t f2tf32(float f) {
    uint32_t u;
    asm volatile("cvt.rna.tf32.f32 %0, %1;\n" : "=r"(u) : "f"(f));
    return u;
}

#define MMA_TF32(d, a, b)                                                      \
    asm volatile(                                                              \
        "mma.sync.aligned.m16n8k8.row.col.f32.tf32.tf32.f32 "                  \
        "{%0,%1,%2,%3},{%4,%5,%6,%7},{%8,%9},{%0,%1,%2,%3};"                   \
        : "+f"(d[0]), "+f"(d[1]), "+f"(d[2]), "+f"(d[3])                       \
        : "r"(a[0]), "r"(a[1]), "r"(a[2]), "r"(a[3]), "r"(b[0]), "r"(b[1]))

__global__ void __launch_bounds__(256) k_gemm(const float* __restrict__ W,
                                              const float* __restrict__ bias) {
    const int ASTR = 20;
    const int BSTR = 136;
    __shared__ uint32_t As[128 * ASTR];
    __shared__ uint32_t Bs[16 * BSTR];

    int tid = threadIdx.x;
    int warp = tid >> 5, lane = tid & 31;
    int r = lane >> 2, c = lane & 3;
    int wm = (warp >> 2) * 64;
    int wn = (warp & 3) * 32;
    int bR = blockIdx.y, bC = blockIdx.x;

    float acc[4][4][4];
#pragma unroll
    for (int i = 0; i < 4; i++)
#pragma unroll
        for (int j = 0; j < 4; j++)
#pragma unroll
            for (int q = 0; q < 4; q++) acc[i][j][q] = 0.f;

    for (int k0 = 0; k0 < DD; k0 += 16) {
#pragma unroll
        for (int i = 0; i < 2; i++) {
            int idx = tid + i * 256;
            int m = idx >> 2;
            int kk = (idx & 3) * 4;
            int grow = bR * 128 + m;
            float4 v = (grow < NN)
                           ? *(const float4*)(g_X + grow * DD + k0 + kk)
                           : make_float4(0.f, 0.f, 0.f, 0.f);
            As[m * ASTR + kk + 0] = f2tf32(v.x);
            As[m * ASTR + kk + 1] = f2tf32(v.y);
            As[m * ASTR + kk + 2] = f2tf32(v.z);
            As[m * ASTR + kk + 3] = f2tf32(v.w);
        }
#pragma unroll
        for (int i = 0; i < 2; i++) {
            int idx = tid + i * 256;
            int kr = idx >> 5;
            int c4 = (idx & 31) * 4;
            float4 v = *(const float4*)(W + (k0 + kr) * DD + bC * 128 + c4);
            Bs[kr * BSTR + c4 + 0] = f2tf32(v.x);
            Bs[kr * BSTR + c4 + 1] = f2tf32(v.y);
            Bs[kr * BSTR + c4 + 2] = f2tf32(v.z);
            Bs[kr * BSTR + c4 + 3] = f2tf32(v.w);
        }
        __syncthreads();

#pragma unroll
        for (int ks = 0; ks < 16; ks += 8) {
            uint32_t a[4][4], b[4][2];
#pragma unroll
            for (int ti = 0; ti < 4; ti++) {
                int m0 = wm + ti * 16;
                a[ti][0] = As[(m0 + r) * ASTR + ks + c];
                a[ti][1] = As[(m0 + r + 8) * ASTR + ks + c];
                a[ti][2] = As[(m0 + r) * ASTR + ks + c + 4];
                a[ti][3] = As[(m0 + r + 8) * ASTR + ks + c + 4];
            }
#pragma unroll
            for (int tj = 0; tj < 4; tj++) {
                int n0 = wn + tj * 8 + r;
                b[tj][0] = Bs[(ks + c) * BSTR + n0];
                b[tj][1] = Bs[(ks + c + 4) * BSTR + n0];
            }
#pragma unroll
            for (int ti = 0; ti < 4; ti++)
#pragma unroll
                for (int tj = 0; tj < 4; tj++) MMA_TF32(acc[ti][tj], a[ti], b[tj]);
        }
        __syncthreads();
    }

    // epilogue: HSH = fp16( (acc + bias) * dis[row] )
#pragma unroll
    for (int ti = 0; ti < 4; ti++) {
        int row0 = bR * 128 + wm + ti * 16 + r;
        int row1 = row0 + 8;
        float dis0 = (row0 < NN) ? g_DIS[row0] : 0.f;
        float dis1 = (row1 < NN) ? g_DIS[row1] : 0.f;
#pragma unroll
        for (int tj = 0; tj < 4; tj++) {
            int col = bC * 128 + wn + tj * 8 + 2 * c;
            float bx = __ldg(bias + col), by = __ldg(bias + col + 1);
            if (row0 < NN) {
                __half2 h = __floats2half2_rn((acc[ti][tj][0] + bx) * dis0,
                                              (acc[ti][tj][1] + by) * dis0);
                *(__half2*)(g_HSH + row0 * DD + col) = h;
            }
            if (row1 < NN) {
                __half2 h = __floats2half2_rn((acc[ti][tj][2] + bx) * dis1,
                                              (acc[ti][tj][3] + by) * dis1);
                *(__half2*)(g_HSH + row1 * DD + col) = h;
            }
        }
    }
}

// ---------------- aggregation: warp per node, fp16 rows (512B) ----------------
// one LDG.128 per lane per edge; fp32 accumulate.
// LAYER1: g_X = relu(dis*(sum + HS))   LAYER2: g_U = relu(dis*(sum + HS))
template <int LAYER1>
__global__ void __launch_bounds__(256) k_agg() {
    int w = (blockIdx.x * blockDim.x + threadIdx.x) >> 5;
    int lane = threadIdx.x & 31;
    if (w >= NN) return;
    int s = g_ROWPTR[w], e = g_ROWPTR[w + 1];
    const uint4* HS = (const uint4*)g_HSH;  // row stride = 32 uint4 (512B)
    float acc[8];
#pragma unroll
    for (int q = 0; q < 8; q++) acc[q] = 0.f;

    for (int base = s; base < e; base += 32) {
        int cnt = e - base; if (cnt > 32) cnt = 32;
        int mysrc = (lane < cnt) ? g_CSRC[base + lane] : 0;
#pragma unroll 4
        for (int i = 0; i < cnt; i++) {
            int src = __shfl_sync(0xffffffffu, mysrc, i);
            uint4 v = __ldg(HS + src * 32 + lane);
            float2 f0 = __half22float2(*(__half2*)&v.x);
            float2 f1 = __half22float2(*(__half2*)&v.y);
            float2 f2 = __half22float2(*(__half2*)&v.z);
            float2 f3 = __half22float2(*(__half2*)&v.w);
            acc[0] += f0.x; acc[1] += f0.y;
            acc[2] += f1.x; acc[3] += f1.y;
            acc[4] += f2.x; acc[5] += f2.y;
            acc[6] += f3.x; acc[7] += f3.y;
        }
    }
    // self-loop + finalize
    uint4 sv = __ldg(HS + w * 32 + lane);
    float2 s0 = __half22float2(*(__half2*)&sv.x);
    float2 s1 = __half22float2(*(__half2*)&sv.y);
    float2 s2 = __half22float2(*(__half2*)&sv.z);
    float2 s3 = __half22float2(*(__half2*)&sv.w);
    float dis = g_DIS[w];
    float o[8];
    o[0] = fmaxf(dis * (acc[0] + s0.x), 0.f);
    o[1] = fmaxf(dis * (acc[1] + s0.y), 0.f);
    o[2] = fmaxf(dis * (acc[2] + s1.x), 0.f);
    o[3] = fmaxf(dis * (acc[3] + s1.y), 0.f);
    o[4] = fmaxf(dis * (acc[4] + s2.x), 0.f);
    o[5] = fmaxf(dis * (acc[5] + s2.y), 0.f);
    o[6] = fmaxf(dis * (acc[6] + s3.x), 0.f);
    o[7] = fmaxf(dis * (acc[7] + s3.y), 0.f);
    float4* OUT4 = LAYER1 ? (float4*)g_X : (float4*)g_U;
    OUT4[w * 64 + lane * 2 + 0] = make_float4(o[0], o[1], o[2], o[3]);
    OUT4[w * 64 + lane * 2 + 1] = make_float4(o[4], o[5], o[6], o[7]);
}

// graph boundaries via binary search on sorted batch ids
__global__ void k_gstart(const int* __restrict__ batch) {
    int t = threadIdx.x;
    if (t <= NG) {
        int lo = 0, hi = NN;
        while (lo < hi) {
            int mid = (lo + hi) >> 1;
            if (batch[mid] < t) lo = mid + 1; else hi = mid;
        }
        g_GSTART[t] = lo;
    }
}

// pool pass 1: 8 node-chunks per graph -> partial sums (float4 lanes)
__global__ void k_pool1() {
    int g = blockIdx.x, ch = blockIdx.y;
    int lane = threadIdx.x;  // 64 threads, float4 each
    int s = g_GSTART[g], e = g_GSTART[g + 1];
    int len = e - s;
    int c0 = s + (int)(((long long)len * ch) >> 3);
    int c1 = s + (int)(((long long)len * (ch + 1)) >> 3);
    const float4* U4 = (const float4*)g_U;
    float4 acc = make_float4(0.f, 0.f, 0.f, 0.f);
    for (int n = c0; n < c1; n++) {
        float4 v = __ldg(U4 + n * 64 + lane);
        acc.x += v.x; acc.y += v.y; acc.z += v.z; acc.w += v.w;
    }
    ((float4*)g_PART)[(ch * NG + g) * 64 + lane] = acc;
}

// pool pass 2: reduce the 8 partials
__global__ void k_pool2(float* __restrict__ out) {
    int g = blockIdx.x;
    int lane = threadIdx.x;  // 64
    const float4* P4 = (const float4*)g_PART;
    float4 acc = make_float4(0.f, 0.f, 0.f, 0.f);
#pragma unroll
    for (int ch = 0; ch < 8; ch++) {
        float4 v = P4[(ch * NG + g) * 64 + lane];
        acc.x += v.x; acc.y += v.y; acc.z += v.z; acc.w += v.w;
    }
    ((float4*)out)[g * 64 + lane] = acc;
}

// ---------------- launch ------------------------------------------------------

extern "C" void kernel_launch(void* const* d_in, const int* in_sizes, int n_in,
                              void* d_out, int out_size) {
    const int *seq = nullptr, *edge = nullptr, *batch = nullptr;
    const float *emb = nullptr, *W0 = nullptr, *b0 = nullptr, *W1 = nullptr, *b1 = nullptr;
    for (int i = 0; i < n_in; i++) {
        int s = in_sizes[i];
        if (s == NN * 16)            seq  = (const int*)d_in[i];
        else if (s == 2 * NE)        edge = (const int*)d_in[i];
        else if (s == NN)            batch = (const int*)d_in[i];
        else if (s == VOCAB * DD)    emb  = (const float*)d_in[i];
        else if (s == DD * DD) { if (!W0) W0 = (const float*)d_in[i]; else W1 = (const float*)d_in[i]; }
        else if (s == DD)      { if (!b0) b0 = (const float*)d_in[i]; else b1 = (const float*)d_in[i]; }
    }
    float* out = (float*)d_out;

    const int SB = 196;          // ceil(NN/256)
    const int WB = (NN + 7) / 8; // warp-per-node blocks (8 warps each)

    k_zero_deg<<<(NN + 255) / 256, 256>>>();
    k_embed<<<WB, 256>>>(seq, emb);
    k_count<<<(NE + 255) / 256, 256>>>(edge);
    k_scan1<<<SB, 256>>>();
    k_scan2<<<1, 256>>>();
    k_scan3<<<SB, 256>>>();
    k_fill<<<(NE + 255) / 256, 256>>>(edge);
    k_gstart<<<1, 128>>>(batch);

    dim3 gg(DD / 128, (NN + 127) / 128);
    // layer 1
    k_gemm<<<gg, 256>>>(W0, b0);
    k_agg<1><<<WB, 256>>>();
    // layer 2
    k_gemm<<<gg, 256>>>(W1, b1);
    k_agg<0><<<WB, 256>>>();
    // pool
    dim3 pg(NG, 8);
    k_pool1<<<pg, 64>>>();
    k_pool2<<<NG, 64>>>(out);
}

// round 5
// speedup vs baseline: 2.9211x; 1.1270x over previous
#include <cuda_runtime.h>
#include <cuda_fp16.h>
#include <cstdint>

#define NN 50000
#define NG 64
#define DD 256
#define NE 800000
#define VOCAB 100000

// ---------------- scratch (device globals: no allocation allowed) -------------
__device__ float  g_X[NN * DD];     // layer input (embeddings, then relu(layer1))
__device__ __half g_HSH[NN * DD];   // h * dis (GEMM output, norm-folded), fp16
__device__ float  g_U[NN * DD];     // layer2 final node feats
__device__ float  g_DIS[NN];        // deg^{-1/2}
__device__ int    g_DEG[NN];
__device__ int    g_ROWPTR[NN + 1];
__device__ int    g_CPOS[NN];
__device__ int    g_CSRC[NE];
__device__ int    g_GSTART[NG + 1];
__device__ int    g_BSUM[256];
__device__ float  g_PART[8 * NG * DD];

#define WB  6250   // embed warp-blocks: NN/8
#define CB  3125   // edge blocks: NE/256
#define SB  196    // ceil(NN/256)
#define GB  782    // gemm blocks: 2 * 391

// ---------------- small kernels ----------------------------------------------

__global__ void k_zero_deg() {
    int n = blockIdx.x * blockDim.x + threadIdx.x;
    if (n < NN) g_DEG[n] = 0;
}

// fused: embed (blocks [0,WB)) ∥ degree count (blocks [WB,WB+CB))
__global__ void __launch_bounds__(256) k_embed_count(const int* __restrict__ seq,
                                                     const float* __restrict__ emb,
                                                     const int* __restrict__ edge) {
    if (blockIdx.x < WB) {
        int w = blockIdx.x * 8 + (threadIdx.x >> 5);
        int lane = threadIdx.x & 31;
        if (w >= NN) return;
        int tok = (lane < 16) ? seq[w * 16 + lane] : 0;
        const float4* E4 = (const float4*)emb;
        float4 a0 = make_float4(0.f, 0.f, 0.f, 0.f);
        float4 a1 = make_float4(0.f, 0.f, 0.f, 0.f);
#pragma unroll
        for (int t = 0; t < 16; t++) {
            int tk = __shfl_sync(0xffffffffu, tok, t);
            const float4* row = E4 + tk * 64;
            float4 v0 = __ldg(row + lane);
            float4 v1 = __ldg(row + lane + 32);
            a0.x += v0.x; a0.y += v0.y; a0.z += v0.z; a0.w += v0.w;
            a1.x += v1.x; a1.y += v1.y; a1.z += v1.z; a1.w += v1.w;
        }
        float4* X4 = (float4*)g_X;
        X4[w * 64 + lane] = a0;
        X4[w * 64 + lane + 32] = a1;
    } else {
        int e = (blockIdx.x - WB) * 256 + threadIdx.x;
        if (e < NE) atomicAdd(&g_DEG[edge[NE + e]], 1);
    }
}

// ---- parallel 3-pass exclusive scan of g_DEG ---------------------------------
__device__ __forceinline__ int block_scan_incl(int v, int t) {
    __shared__ int ws[8];
    int x = v;
#pragma unroll
    for (int o = 1; o < 32; o <<= 1) {
        int y = __shfl_up_sync(0xffffffffu, x, o);
        if ((t & 31) >= o) x += y;
    }
    if ((t & 31) == 31) ws[t >> 5] = x;
    __syncthreads();
    if (t < 8) {
        int s = ws[t];
#pragma unroll
        for (int o = 1; o < 8; o <<= 1) {
            int y = __shfl_up_sync(0xffu, s, o);
            if (t >= o) s += y;
        }
        ws[t] = s;
    }
    __syncthreads();
    int offs = (t >= 32) ? ws[(t >> 5) - 1] : 0;
    return x + offs;
}

__global__ void k_scan1() {
    int t = threadIdx.x;
    int i = blockIdx.x * 256 + t;
    int v = (i < NN) ? g_DEG[i] : 0;
    int incl = block_scan_incl(v, t);
    if (i < NN) g_ROWPTR[i] = incl - v;
    if (t == 255) g_BSUM[blockIdx.x] = incl;
}

// scan2 + gstart (both tiny 1-block jobs)
__global__ void k_scan2_gstart(const int* __restrict__ batch) {
    int t = threadIdx.x;
    if (t <= NG) {   // binary search graph boundaries (independent work)
        int lo = 0, hi = NN;
        while (lo < hi) {
            int mid = (lo + hi) >> 1;
            if (batch[mid] < t) lo = mid + 1; else hi = mid;
        }
        g_GSTART[t] = lo;
    }
    int v = (t < SB) ? g_BSUM[t] : 0;
    int incl = block_scan_incl(v, t);
    if (t < SB) g_BSUM[t] = incl - v;
}

__global__ void k_scan3() {
    int t = threadIdx.x;
    int i = blockIdx.x * 256 + t;
    if (i < NN) {
        int rp = g_ROWPTR[i] + g_BSUM[blockIdx.x];
        g_ROWPTR[i] = rp;
        g_CPOS[i] = rp;
        g_DIS[i] = rsqrtf((float)g_DEG[i] + 1.0f);
    }
    if (i == 0) g_ROWPTR[NN] = NE;
}

// ---------------- TF32 tensor-core GEMM (device body) --------------------------
__device__ __forceinline__ uint32_t f2tf32(float f) {
    uint32_t u;
    asm volatile("cvt.rna.tf32.f32 %0, %1;\n" : "=r"(u) : "f"(f));
    return u;
}

#define MMA_TF32(d, a, b)                                                      \
    asm volatile(                                                              \
        "mma.sync.aligned.m16n8k8.row.col.f32.tf32.tf32.f32 "                  \
        "{%0,%1,%2,%3},{%4,%5,%6,%7},{%8,%9},{%0,%1,%2,%3};"                   \
        : "+f"(d[0]), "+f"(d[1]), "+f"(d[2]), "+f"(d[3])                       \
        : "r"(a[0]), "r"(a[1]), "r"(a[2]), "r"(a[3]), "r"(b[0]), "r"(b[1]))

struct GemmSmem {
    uint32_t As[128 * 20];
    uint32_t Bs[16 * 136];
};

__device__ __forceinline__ void gemm_body(const float* __restrict__ W,
                                          const float* __restrict__ bias,
                                          int bR, int bC, GemmSmem* sm) {
    const int ASTR = 20, BSTR = 136;
    int tid = threadIdx.x;
    int warp = tid >> 5, lane = tid & 31;
    int r = lane >> 2, c = lane & 3;
    int wm = (warp >> 2) * 64;
    int wn = (warp & 3) * 32;

    // per-thread load slots
    int mA0 = tid >> 2, kkA = (tid & 3) * 4;           // A slot 0
    int mA1 = mA0 + 64;                                 // A slot 1
    int krB0 = tid >> 5, cB = (tid & 31) * 4;           // B slot 0
    int krB1 = krB0 + 8;                                // B slot 1
    int rowA0 = bR * 128 + mA0, rowA1 = bR * 128 + mA1;

    float acc[4][4][4];
#pragma unroll
    for (int i = 0; i < 4; i++)
#pragma unroll
        for (int j = 0; j < 4; j++)
#pragma unroll
            for (int q = 0; q < 4; q++) acc[i][j][q] = 0.f;

    // prefetch k0 = 0
    float4 va0, va1, vb0, vb1;
    va0 = (rowA0 < NN) ? *(const float4*)(g_X + rowA0 * DD + kkA)
                       : make_float4(0.f, 0.f, 0.f, 0.f);
    va1 = (rowA1 < NN) ? *(const float4*)(g_X + rowA1 * DD + kkA)
                       : make_float4(0.f, 0.f, 0.f, 0.f);
    vb0 = *(const float4*)(W + krB0 * DD + bC * 128 + cB);
    vb1 = *(const float4*)(W + krB1 * DD + bC * 128 + cB);

    for (int k0 = 0; k0 < DD; k0 += 16) {
        // store prefetched tile (cvt to tf32)
        sm->As[mA0 * ASTR + kkA + 0] = f2tf32(va0.x);
        sm->As[mA0 * ASTR + kkA + 1] = f2tf32(va0.y);
        sm->As[mA0 * ASTR + kkA + 2] = f2tf32(va0.z);
        sm->As[mA0 * ASTR + kkA + 3] = f2tf32(va0.w);
        sm->As[mA1 * ASTR + kkA + 0] = f2tf32(va1.x);
        sm->As[mA1 * ASTR + kkA + 1] = f2tf32(va1.y);
        sm->As[mA1 * ASTR + kkA + 2] = f2tf32(va1.z);
        sm->As[mA1 * ASTR + kkA + 3] = f2tf32(va1.w);
        sm->Bs[krB0 * BSTR + cB + 0] = f2tf32(vb0.x);
        sm->Bs[krB0 * BSTR + cB + 1] = f2tf32(vb0.y);
        sm->Bs[krB0 * BSTR + cB + 2] = f2tf32(vb0.z);
        sm->Bs[krB0 * BSTR + cB + 3] = f2tf32(vb0.w);
        sm->Bs[krB1 * BSTR + cB + 0] = f2tf32(vb1.x);
        sm->Bs[krB1 * BSTR + cB + 1] = f2tf32(vb1.y);
        sm->Bs[krB1 * BSTR + cB + 2] = f2tf32(vb1.z);
        sm->Bs[krB1 * BSTR + cB + 3] = f2tf32(vb1.w);
        __syncthreads();

        // issue next tile's loads (overlap with MMAs below)
        int kn = k0 + 16;
        if (kn < DD) {
            va0 = (rowA0 < NN) ? *(const float4*)(g_X + rowA0 * DD + kn + kkA)
                               : make_float4(0.f, 0.f, 0.f, 0.f);
            va1 = (rowA1 < NN) ? *(const float4*)(g_X + rowA1 * DD + kn + kkA)
                               : make_float4(0.f, 0.f, 0.f, 0.f);
            vb0 = *(const float4*)(W + (kn + krB0) * DD + bC * 128 + cB);
            vb1 = *(const float4*)(W + (kn + krB1) * DD + bC * 128 + cB);
        }

#pragma unroll
        for (int ks = 0; ks < 16; ks += 8) {
            uint32_t a[4][4], b[4][2];
#pragma unroll
            for (int ti = 0; ti < 4; ti++) {
                int m0 = wm + ti * 16;
                a[ti][0] = sm->As[(m0 + r) * ASTR + ks + c];
                a[ti][1] = sm->As[(m0 + r + 8) * ASTR + ks + c];
                a[ti][2] = sm->As[(m0 + r) * ASTR + ks + c + 4];
                a[ti][3] = sm->As[(m0 + r + 8) * ASTR + ks + c + 4];
            }
#pragma unroll
            for (int tj = 0; tj < 4; tj++) {
                int n0 = wn + tj * 8 + r;
                b[tj][0] = sm->Bs[(ks + c) * BSTR + n0];
                b[tj][1] = sm->Bs[(ks + c + 4) * BSTR + n0];
            }
#pragma unroll
            for (int ti = 0; ti < 4; ti++)
#pragma unroll
                for (int tj = 0; tj < 4; tj++) MMA_TF32(acc[ti][tj], a[ti], b[tj]);
        }
        __syncthreads();
    }

    // epilogue: HSH = fp16( (acc + bias) * dis[row] )
#pragma unroll
    for (int ti = 0; ti < 4; ti++) {
        int row0 = bR * 128 + wm + ti * 16 + r;
        int row1 = row0 + 8;
        float dis0 = (row0 < NN) ? g_DIS[row0] : 0.f;
        float dis1 = (row1 < NN) ? g_DIS[row1] : 0.f;
#pragma unroll
        for (int tj = 0; tj < 4; tj++) {
            int col = bC * 128 + wn + tj * 8 + 2 * c;
            float bx = __ldg(bias + col), by = __ldg(bias + col + 1);
            if (row0 < NN) {
                __half2 h = __floats2half2_rn((acc[ti][tj][0] + bx) * dis0,
                                              (acc[ti][tj][1] + by) * dis0);
                *(__half2*)(g_HSH + row0 * DD + col) = h;
            }
            if (row1 < NN) {
                __half2 h = __floats2half2_rn((acc[ti][tj][2] + bx) * dis1,
                                              (acc[ti][tj][3] + by) * dis1);
                *(__half2*)(g_HSH + row1 * DD + col) = h;
            }
        }
    }
}

// fused: layer-1 GEMM (blocks [0,GB)) ∥ CSR fill (blocks [GB,GB+CB))
__global__ void __launch_bounds__(256) k_gemm_fill(const float* __restrict__ W,
                                                   const float* __restrict__ bias,
                                                   const int* __restrict__ edge) {
    __shared__ GemmSmem sm;
    if (blockIdx.x < GB) {
        gemm_body(W, bias, blockIdx.x >> 1, blockIdx.x & 1, &sm);
    } else {
        int e = (blockIdx.x - GB) * 256 + threadIdx.x;
        if (e < NE) {
            int dst = edge[NE + e];
            int p = atomicAdd(&g_CPOS[dst], 1);
            g_CSRC[p] = edge[e];
        }
    }
}

// plain GEMM (layer 2)
__global__ void __launch_bounds__(256) k_gemm(const float* __restrict__ W,
                                              const float* __restrict__ bias) {
    __shared__ GemmSmem sm;
    gemm_body(W, bias, blockIdx.y, blockIdx.x, &sm);
}

// ---------------- aggregation: warp per node, fp16 rows (512B) ----------------
template <int LAYER1>
__global__ void __launch_bounds__(256) k_agg() {
    int w = (blockIdx.x * blockDim.x + threadIdx.x) >> 5;
    int lane = threadIdx.x & 31;
    if (w >= NN) return;
    int s = g_ROWPTR[w], e = g_ROWPTR[w + 1];
    const uint4* HS = (const uint4*)g_HSH;  // row stride = 32 uint4 (512B)
    float acc[8];
#pragma unroll
    for (int q = 0; q < 8; q++) acc[q] = 0.f;

    for (int base = s; base < e; base += 32) {
        int cnt = e - base; if (cnt > 32) cnt = 32;
        int mysrc = (lane < cnt) ? g_CSRC[base + lane] : 0;
#pragma unroll 4
        for (int i = 0; i < cnt; i++) {
            int src = __shfl_sync(0xffffffffu, mysrc, i);
            uint4 v = __ldg(HS + src * 32 + lane);
            float2 f0 = __half22float2(*(__half2*)&v.x);
            float2 f1 = __half22float2(*(__half2*)&v.y);
            float2 f2 = __half22float2(*(__half2*)&v.z);
            float2 f3 = __half22float2(*(__half2*)&v.w);
            acc[0] += f0.x; acc[1] += f0.y;
            acc[2] += f1.x; acc[3] += f1.y;
            acc[4] += f2.x; acc[5] += f2.y;
            acc[6] += f3.x; acc[7] += f3.y;
        }
    }
    uint4 sv = __ldg(HS + w * 32 + lane);
    float2 s0 = __half22float2(*(__half2*)&sv.x);
    float2 s1 = __half22float2(*(__half2*)&sv.y);
    float2 s2 = __half22float2(*(__half2*)&sv.z);
    float2 s3 = __half22float2(*(__half2*)&sv.w);
    float dis = g_DIS[w];
    float o[8];
    o[0] = fmaxf(dis * (acc[0] + s0.x), 0.f);
    o[1] = fmaxf(dis * (acc[1] + s0.y), 0.f);
    o[2] = fmaxf(dis * (acc[2] + s1.x), 0.f);
    o[3] = fmaxf(dis * (acc[3] + s1.y), 0.f);
    o[4] = fmaxf(dis * (acc[4] + s2.x), 0.f);
    o[5] = fmaxf(dis * (acc[5] + s2.y), 0.f);
    o[6] = fmaxf(dis * (acc[6] + s3.x), 0.f);
    o[7] = fmaxf(dis * (acc[7] + s3.y), 0.f);
    float4* OUT4 = LAYER1 ? (float4*)g_X : (float4*)g_U;
    OUT4[w * 64 + lane * 2 + 0] = make_float4(o[0], o[1], o[2], o[3]);
    OUT4[w * 64 + lane * 2 + 1] = make_float4(o[4], o[5], o[6], o[7]);
}

// pool pass 1: 8 node-chunks per graph -> partial sums
__global__ void k_pool1() {
    int g = blockIdx.x, ch = blockIdx.y;
    int lane = threadIdx.x;
    int s = g_GSTART[g], e = g_GSTART[g + 1];
    int len = e - s;
    int c0 = s + (int)(((long long)len * ch) >> 3);
    int c1 = s + (int)(((long long)len * (ch + 1)) >> 3);
    const float4* U4 = (const float4*)g_U;
    float4 acc = make_float4(0.f, 0.f, 0.f, 0.f);
    for (int n = c0; n < c1; n++) {
        float4 v = __ldg(U4 + n * 64 + lane);
        acc.x += v.x; acc.y += v.y; acc.z += v.z; acc.w += v.w;
    }
    ((float4*)g_PART)[(ch * NG + g) * 64 + lane] = acc;
}

__global__ void k_pool2(float* __restrict__ out) {
    int g = blockIdx.x;
    int lane = threadIdx.x;
    const float4* P4 = (const float4*)g_PART;
    float4 acc = make_float4(0.f, 0.f, 0.f, 0.f);
#pragma unroll
    for (int ch = 0; ch < 8; ch++) {
        float4 v = P4[(ch * NG + g) * 64 + lane];
        acc.x += v.x; acc.y += v.y; acc.z += v.z; acc.w += v.w;
    }
    ((float4*)out)[g * 64 + lane] = acc;
}

// ---------------- launch ------------------------------------------------------

extern "C" void kernel_launch(void* const* d_in, const int* in_sizes, int n_in,
                              void* d_out, int out_size) {
    const int *seq = nullptr, *edge = nullptr, *batch = nullptr;
    const float *emb = nullptr, *W0 = nullptr, *b0 = nullptr, *W1 = nullptr, *b1 = nullptr;
    for (int i = 0; i < n_in; i++) {
        int s = in_sizes[i];
        if (s == NN * 16)            seq  = (const int*)d_in[i];
        else if (s == 2 * NE)        edge = (const int*)d_in[i];
        else if (s == NN)            batch = (const int*)d_in[i];
        else if (s == VOCAB * DD)    emb  = (const float*)d_in[i];
        else if (s == DD * DD) { if (!W0) W0 = (const float*)d_in[i]; else W1 = (const float*)d_in[i]; }
        else if (s == DD)      { if (!b0) b0 = (const float*)d_in[i]; else b1 = (const float*)d_in[i]; }
    }
    float* out = (float*)d_out;

    k_zero_deg<<<SB, 256>>>();
    k_embed_count<<<WB + CB, 256>>>(seq, emb, edge);
    k_scan1<<<SB, 256>>>();
    k_scan2_gstart<<<1, 256>>>(batch);
    k_scan3<<<SB, 256>>>();

    // layer 1 GEMM ∥ CSR fill (both only depend on scan3/embed)
    k_gemm_fill<<<GB + CB, 256>>>(W0, b0, edge);
    k_agg<1><<<WB, 256>>>();
    // layer 2
    dim3 gg(2, 391);
    k_gemm<<<gg, 256>>>(W1, b1);
    k_agg<0><<<WB, 256>>>();
    // pool
    dim3 pg(NG, 8);
    k_pool1<<<pg, 64>>>();
    k_pool2<<<NG, 64>>>(out);
}

// round 6
// speedup vs baseline: 3.2963x; 1.1285x over previous
#include <cuda_runtime.h>
#include <cuda_fp16.h>
#include <cstdint>

#define NN 50000
#define NG 64
#define DD 256
#define NE 800000
#define VOCAB 100000

// ---------------- scratch (device globals: no allocation allowed) -------------
__device__ __half g_XH[NN * DD];    // layer input fp16 (embeddings, then relu(l1))
__device__ __half g_HSH[NN * DD];   // h * dis (GEMM output, norm-folded), fp16
__device__ float  g_U[NN * DD];     // layer2 final node feats (fp32 for pool)
__device__ float  g_DIS[NN];        // deg^{-1/2}
__device__ int    g_DEG[NN];
__device__ int    g_ROWPTR[NN + 1];
__device__ int    g_CPOS[NN];
__device__ int    g_CSRC[NE];
__device__ int    g_GSTART[NG + 1];
__device__ int    g_BSUM[256];
__device__ float  g_PART[8 * NG * DD];

#define WB  6250   // embed warp-blocks: NN/8
#define CB  3125   // edge blocks: NE/256
#define SB  196    // ceil(NN/256)
#define GB  782    // gemm blocks: 2 * 391

// ---------------- small kernels ----------------------------------------------

// zero degree + graph-boundary binary search (gstart only needs `batch`)
__global__ void k_zero_gstart(const int* __restrict__ batch) {
    int n = blockIdx.x * blockDim.x + threadIdx.x;
    if (n < NN) g_DEG[n] = 0;
    if (blockIdx.x == 0 && threadIdx.x <= NG) {
        int t = threadIdx.x;
        int lo = 0, hi = NN;
        while (lo < hi) {
            int mid = (lo + hi) >> 1;
            if (__ldg(batch + mid) < t) lo = mid + 1; else hi = mid;
        }
        g_GSTART[t] = lo;
    }
}

// fused: embed (blocks [0,WB)) ∥ degree count (blocks [WB,WB+CB))
// x[n,:] = fp16( sum_t emb[seq[n,t],:] )  — warp per node, lane = 8 cols
__global__ void __launch_bounds__(256) k_embed_count(const int* __restrict__ seq,
                                                     const float* __restrict__ emb,
                                                     const int* __restrict__ edge) {
    if (blockIdx.x < WB) {
        int w = blockIdx.x * 8 + (threadIdx.x >> 5);
        int lane = threadIdx.x & 31;
        if (w >= NN) return;
        int tok = (lane < 16) ? seq[w * 16 + lane] : 0;
        const float4* E4 = (const float4*)emb;
        float4 a0 = make_float4(0.f, 0.f, 0.f, 0.f);
        float4 a1 = make_float4(0.f, 0.f, 0.f, 0.f);
#pragma unroll
        for (int t = 0; t < 16; t++) {
            int tk = __shfl_sync(0xffffffffu, tok, t);
            const float4* row = E4 + tk * 64;
            float4 v0 = __ldg(row + 2 * lane);
            float4 v1 = __ldg(row + 2 * lane + 1);
            a0.x += v0.x; a0.y += v0.y; a0.z += v0.z; a0.w += v0.w;
            a1.x += v1.x; a1.y += v1.y; a1.z += v1.z; a1.w += v1.w;
        }
        union { uint4 u; __half2 h2[4]; } pk;
        pk.h2[0] = __floats2half2_rn(a0.x, a0.y);
        pk.h2[1] = __floats2half2_rn(a0.z, a0.w);
        pk.h2[2] = __floats2half2_rn(a1.x, a1.y);
        pk.h2[3] = __floats2half2_rn(a1.z, a1.w);
        ((uint4*)g_XH)[w * 32 + lane] = pk.u;
    } else {
        int e = (blockIdx.x - WB) * 256 + threadIdx.x;
        if (e < NE) atomicAdd(&g_DEG[edge[NE + e]], 1);
    }
}

// ---- parallel 3-pass exclusive scan of g_DEG ---------------------------------
__device__ __forceinline__ int block_scan_incl(int v, int t) {
    __shared__ int ws[8];
    int x = v;
#pragma unroll
    for (int o = 1; o < 32; o <<= 1) {
        int y = __shfl_up_sync(0xffffffffu, x, o);
        if ((t & 31) >= o) x += y;
    }
    if ((t & 31) == 31) ws[t >> 5] = x;
    __syncthreads();
    if (t < 8) {
        int s = ws[t];
#pragma unroll
        for (int o = 1; o < 8; o <<= 1) {
            int y = __shfl_up_sync(0xffu, s, o);
            if (t >= o) s += y;
        }
        ws[t] = s;
    }
    __syncthreads();
    int offs = (t >= 32) ? ws[(t >> 5) - 1] : 0;
    return x + offs;
}

__global__ void k_scan1() {
    int t = threadIdx.x;
    int i = blockIdx.x * 256 + t;
    int v = (i < NN) ? g_DEG[i] : 0;
    int incl = block_scan_incl(v, t);
    if (i < NN) g_ROWPTR[i] = incl - v;
    if (t == 255) g_BSUM[blockIdx.x] = incl;
}

__global__ void k_scan2() {
    int t = threadIdx.x;
    int v = (t < SB) ? g_BSUM[t] : 0;
    int incl = block_scan_incl(v, t);
    if (t < SB) g_BSUM[t] = incl - v;
}

__global__ void k_scan3() {
    int t = threadIdx.x;
    int i = blockIdx.x * 256 + t;
    if (i < NN) {
        int rp = g_ROWPTR[i] + g_BSUM[blockIdx.x];
        g_ROWPTR[i] = rp;
        g_CPOS[i] = rp;
        g_DIS[i] = rsqrtf((float)g_DEG[i] + 1.0f);
    }
    if (i == 0) g_ROWPTR[NN] = NE;
}

// ---------------- FP16 tensor-core GEMM ---------------------------------------
#define MMA_F16(d, a, b)                                                       \
    asm volatile(                                                              \
        "mma.sync.aligned.m16n8k16.row.col.f32.f16.f16.f32 "                   \
        "{%0,%1,%2,%3},{%4,%5,%6,%7},{%8,%9},{%0,%1,%2,%3};"                   \
        : "+f"(d[0]), "+f"(d[1]), "+f"(d[2]), "+f"(d[3])                       \
        : "r"(a[0]), "r"(a[1]), "r"(a[2]), "r"(a[3]), "r"(b[0]), "r"(b[1]))

struct __align__(16) GemmSmem {
    __half As[128 * 24];   // [m][k], 24-half row stride (conflict-free frags)
    __half Bs[128 * 24];   // [n][k] (transposed W tile)
};

__device__ __forceinline__ void gemm_body(const float* __restrict__ W,
                                          const float* __restrict__ bias,
                                          int bR, int bC, GemmSmem* sm) {
    int tid = threadIdx.x;
    int warp = tid >> 5, lane = tid & 31;
    int r = lane >> 2, c = lane & 3;
    int wm = (warp >> 2) * 64;
    int wn = (warp & 3) * 32;

    int mA = tid >> 1, kA = (tid & 1) * 8;
    int rowA = bR * 128 + mA;
    int nB = tid & 127, kB = (tid >> 7) * 8;
    const float* Wcol = W + bC * 128 + nB;

    float acc[4][4][4];
#pragma unroll
    for (int i = 0; i < 4; i++)
#pragma unroll
        for (int j = 0; j < 4; j++)
#pragma unroll
            for (int q = 0; q < 4; q++) acc[i][j][q] = 0.f;

    uint4 va = (rowA < NN) ? *(const uint4*)(g_XH + rowA * DD + kA)
                           : make_uint4(0u, 0u, 0u, 0u);
    float fb[8];
#pragma unroll
    for (int j = 0; j < 8; j++) fb[j] = __ldg(Wcol + (kB + j) * DD);

    const uint32_t* A32 = (const uint32_t*)sm->As;
    const uint32_t* B32 = (const uint32_t*)sm->Bs;

    for (int k0 = 0; k0 < DD; k0 += 16) {
        *(uint4*)&sm->As[mA * 24 + kA] = va;
        union { uint4 u; __half2 h2[4]; } pk;
        pk.h2[0] = __floats2half2_rn(fb[0], fb[1]);
        pk.h2[1] = __floats2half2_rn(fb[2], fb[3]);
        pk.h2[2] = __floats2half2_rn(fb[4], fb[5]);
        pk.h2[3] = __floats2half2_rn(fb[6], fb[7]);
        *(uint4*)&sm->Bs[nB * 24 + kB] = pk.u;
        __syncthreads();

        int kn = k0 + 16;
        if (kn < DD) {
            va = (rowA < NN) ? *(const uint4*)(g_XH + rowA * DD + kn + kA)
                             : make_uint4(0u, 0u, 0u, 0u);
#pragma unroll
            for (int j = 0; j < 8; j++) fb[j] = __ldg(Wcol + (kn + kB + j) * DD);
        }

        uint32_t a[4][4], b[4][2];
#pragma unroll
        for (int ti = 0; ti < 4; ti++) {
            int m0 = wm + ti * 16;
            a[ti][0] = A32[(m0 + r) * 12 + c];
            a[ti][1] = A32[(m0 + r + 8) * 12 + c];
            a[ti][2] = A32[(m0 + r) * 12 + c + 4];
            a[ti][3] = A32[(m0 + r + 8) * 12 + c + 4];
        }
#pragma unroll
        for (int tj = 0; tj < 4; tj++) {
            int n0 = wn + tj * 8 + r;
            b[tj][0] = B32[n0 * 12 + c];
            b[tj][1] = B32[n0 * 12 + c + 4];
        }
#pragma unroll
        for (int ti = 0; ti < 4; ti++)
#pragma unroll
            for (int tj = 0; tj < 4; tj++) MMA_F16(acc[ti][tj], a[ti], b[tj]);
        __syncthreads();
    }

#pragma unroll
    for (int ti = 0; ti < 4; ti++) {
        int row0 = bR * 128 + wm + ti * 16 + r;
        int row1 = row0 + 8;
        float dis0 = (row0 < NN) ? g_DIS[row0] : 0.f;
        float dis1 = (row1 < NN) ? g_DIS[row1] : 0.f;
#pragma unroll
        for (int tj = 0; tj < 4; tj++) {
            int col = bC * 128 + wn + tj * 8 + 2 * c;
            float bx = __ldg(bias + col), by = __ldg(bias + col + 1);
            if (row0 < NN) {
                __half2 h = __floats2half2_rn((acc[ti][tj][0] + bx) * dis0,
                                              (acc[ti][tj][1] + by) * dis0);
                *(__half2*)(g_HSH + row0 * DD + col) = h;
            }
            if (row1 < NN) {
                __half2 h = __floats2half2_rn((acc[ti][tj][2] + bx) * dis1,
                                              (acc[ti][tj][3] + by) * dis1);
                *(__half2*)(g_HSH + row1 * DD + col) = h;
            }
        }
    }
}

// fused: layer-1 GEMM (blocks [0,GB)) ∥ CSR fill (blocks [GB,GB+CB))
__global__ void __launch_bounds__(256) k_gemm_fill(const float* __restrict__ W,
                                                   const float* __restrict__ bias,
                                                   const int* __restrict__ edge) {
    __shared__ GemmSmem sm;
    if (blockIdx.x < GB) {
        gemm_body(W, bias, blockIdx.x >> 1, blockIdx.x & 1, &sm);
    } else {
        int e = (blockIdx.x - GB) * 256 + threadIdx.x;
        if (e < NE) {
            int dst = edge[NE + e];
            int p = atomicAdd(&g_CPOS[dst], 1);
            g_CSRC[p] = edge[e];
        }
    }
}

__global__ void __launch_bounds__(256) k_gemm(const float* __restrict__ W,
                                              const float* __restrict__ bias) {
    __shared__ GemmSmem sm;
    gemm_body(W, bias, blockIdx.y, blockIdx.x, &sm);
}

// ---------------- aggregation: warp per node, fp16 rows (512B) ----------------
template <int LAYER1>
__global__ void __launch_bounds__(256) k_agg() {
    int w = (blockIdx.x * blockDim.x + threadIdx.x) >> 5;
    int lane = threadIdx.x & 31;
    if (w >= NN) return;
    int s = g_ROWPTR[w], e = g_ROWPTR[w + 1];
    const uint4* HS = (const uint4*)g_HSH;
    float acc[8];
#pragma unroll
    for (int q = 0; q < 8; q++) acc[q] = 0.f;

    for (int base = s; base < e; base += 32) {
        int cnt = e - base; if (cnt > 32) cnt = 32;
        int mysrc = (lane < cnt) ? g_CSRC[base + lane] : 0;
#pragma unroll 4
        for (int i = 0; i < cnt; i++) {
            int src = __shfl_sync(0xffffffffu, mysrc, i);
            uint4 v = __ldg(HS + src * 32 + lane);
            float2 f0 = __half22float2(*(__half2*)&v.x);
            float2 f1 = __half22float2(*(__half2*)&v.y);
            float2 f2 = __half22float2(*(__half2*)&v.z);
            float2 f3 = __half22float2(*(__half2*)&v.w);
            acc[0] += f0.x; acc[1] += f0.y;
            acc[2] += f1.x; acc[3] += f1.y;
            acc[4] += f2.x; acc[5] += f2.y;
            acc[6] += f3.x; acc[7] += f3.y;
        }
    }
    uint4 sv = __ldg(HS + w * 32 + lane);
    float2 s0 = __half22float2(*(__half2*)&sv.x);
    float2 s1 = __half22float2(*(__half2*)&sv.y);
    float2 s2 = __half22float2(*(__half2*)&sv.z);
    float2 s3 = __half22float2(*(__half2*)&sv.w);
    float dis = g_DIS[w];
    float o[8];
    o[0] = fmaxf(dis * (acc[0] + s0.x), 0.f);
    o[1] = fmaxf(dis * (acc[1] + s0.y), 0.f);
    o[2] = fmaxf(dis * (acc[2] + s1.x), 0.f);
    o[3] = fmaxf(dis * (acc[3] + s1.y), 0.f);
    o[4] = fmaxf(dis * (acc[4] + s2.x), 0.f);
    o[5] = fmaxf(dis * (acc[5] + s2.y), 0.f);
    o[6] = fmaxf(dis * (acc[6] + s3.x), 0.f);
    o[7] = fmaxf(dis * (acc[7] + s3.y), 0.f);
    if (LAYER1) {
        union { uint4 u; __half2 h2[4]; } pk;
        pk.h2[0] = __floats2half2_rn(o[0], o[1]);
        pk.h2[1] = __floats2half2_rn(o[2], o[3]);
        pk.h2[2] = __floats2half2_rn(o[4], o[5]);
        pk.h2[3] = __floats2half2_rn(o[6], o[7]);
        ((uint4*)g_XH)[w * 32 + lane] = pk.u;
    } else {
        float4* OUT4 = (float4*)g_U;
        OUT4[w * 64 + lane * 2 + 0] = make_float4(o[0], o[1], o[2], o[3]);
        OUT4[w * 64 + lane * 2 + 1] = make_float4(o[4], o[5], o[6], o[7]);
    }
}

// pool pass 1: 8 node-chunks per graph -> partial sums
__global__ void k_pool1() {
    int g = blockIdx.x, ch = blockIdx.y;
    int lane = threadIdx.x;
    int s = g_GSTART[g], e = g_GSTART[g + 1];
    int len = e - s;
    int c0 = s + (int)(((long long)len * ch) >> 3);
    int c1 = s + (int)(((long long)len * (ch + 1)) >> 3);
    const float4* U4 = (const float4*)g_U;
    float4 acc = make_float4(0.f, 0.f, 0.f, 0.f);
    for (int n = c0; n < c1; n++) {
        float4 v = __ldg(U4 + n * 64 + lane);
        acc.x += v.x; acc.y += v.y; acc.z += v.z; acc.w += v.w;
    }
    ((float4*)g_PART)[(ch * NG + g) * 64 + lane] = acc;
}

__global__ void k_pool2(float* __restrict__ out) {
    int g = blockIdx.x;
    int lane = threadIdx.x;
    const float4* P4 = (const float4*)g_PART;
    float4 acc = make_float4(0.f, 0.f, 0.f, 0.f);
#pragma unroll
    for (int ch = 0; ch < 8; ch++) {
        float4 v = P4[(ch * NG + g) * 64 + lane];
        acc.x += v.x; acc.y += v.y; acc.z += v.z; acc.w += v.w;
    }
    ((float4*)out)[g * 64 + lane] = acc;
}

// ---------------- launch ------------------------------------------------------

extern "C" void kernel_launch(void* const* d_in, const int* in_sizes, int n_in,
                              void* d_out, int out_size) {
    const int *seq = nullptr, *edge = nullptr, *batch = nullptr;
    const float *emb = nullptr, *W0 = nullptr, *b0 = nullptr, *W1 = nullptr, *b1 = nullptr;
    for (int i = 0; i < n_in; i++) {
        int s = in_sizes[i];
        if (s == NN * 16)            seq  = (const int*)d_in[i];
        else if (s == 2 * NE)        edge = (const int*)d_in[i];
        else if (s == NN)            batch = (const int*)d_in[i];
        else if (s == VOCAB * DD)    emb  = (const float*)d_in[i];
        else if (s == DD * DD) { if (!W0) W0 = (const float*)d_in[i]; else W1 = (const float*)d_in[i]; }
        else if (s == DD)      { if (!b0) b0 = (const float*)d_in[i]; else b1 = (const float*)d_in[i]; }
    }
    float* out = (float*)d_out;

    k_zero_gstart<<<SB, 256>>>(batch);
    k_embed_count<<<WB + CB, 256>>>(seq, emb, edge);
    k_scan1<<<SB, 256>>>();
    k_scan2<<<1, 256>>>();
    k_scan3<<<SB, 256>>>();

    // layer 1 GEMM ∥ CSR fill
    k_gemm_fill<<<GB + CB, 256>>>(W0, b0, edge);
    k_agg<1><<<WB, 256>>>();
    // layer 2
    dim3 gg(2, 391);
    k_gemm<<<gg, 256>>>(W1, b1);
    k_agg<0><<<WB, 256>>>();
    // pool
    dim3 pg(NG, 8);
    k_pool1<<<pg, 64>>>();
    k_pool2<<<NG, 64>>>(out);
}

// round 7
// speedup vs baseline: 3.3987x; 1.0310x over previous
#include <cuda_runtime.h>
#include <cuda_fp16.h>
#include <cstdint>

#define NN 50000
#define NG 64
#define DD 256
#define NE 800000
#define VOCAB 100000

#define WB  6250   // embed warp-blocks: NN/8
#define CB  3125   // edge blocks: NE/256
#define SB  196    // ceil(NN/256)
#define GB  782    // gemm blocks: 2 * 391
#define VB  12500  // emb-convert blocks: VOCAB/8

// ---------------- scratch (device globals: no allocation allowed) -------------
__device__ __half g_EMBH[VOCAB * DD];  // fp16 embedding table (per-call convert)
__device__ __half g_XH[NN * DD];       // layer input fp16
__device__ __half g_HSH[NN * DD];      // h * dis (GEMM out, norm-folded), fp16
__device__ float  g_U[NN * DD];        // layer2 final node feats (fp32 for pool)
__device__ float  g_DIS[NN];           // deg^{-1/2}
__device__ int    g_DEG[NN];
__device__ int    g_ROWPTR[NN + 1];
__device__ int    g_CPOS[NN];
__device__ int    g_CSRC[NE];
__device__ int    g_GSTART[NG + 1];
__device__ float  g_PART[8 * NG * DD];
// decoupled-lookback scan state
__device__ unsigned long long g_STATE[SB];  // hi32: flag(0/1/2), lo32: value
__device__ int    g_TICKET;

// ---------------- prep: emb->fp16 convert ∥ zero deg/state ∥ gstart -----------
__global__ void __launch_bounds__(256) k_prep(const int* __restrict__ batch,
                                              const float* __restrict__ emb) {
    if (blockIdx.x < VB) {
        int row = blockIdx.x * 8 + (threadIdx.x >> 5);
        int lane = threadIdx.x & 31;
        const float4* src = (const float4*)emb + row * 64;
        float4 v0 = __ldg(src + 2 * lane);
        float4 v1 = __ldg(src + 2 * lane + 1);
        union { uint4 u; __half2 h2[4]; } pk;
        pk.h2[0] = __floats2half2_rn(v0.x, v0.y);
        pk.h2[1] = __floats2half2_rn(v0.z, v0.w);
        pk.h2[2] = __floats2half2_rn(v1.x, v1.y);
        pk.h2[3] = __floats2half2_rn(v1.z, v1.w);
        ((uint4*)g_EMBH)[row * 32 + lane] = pk.u;
    } else {
        int b = blockIdx.x - VB;
        int t = threadIdx.x;
        int n = b * 256 + t;
        if (n < NN) g_DEG[n] = 0;
        if (b == 0) {
            if (t < SB) g_STATE[t] = 0ull;
            if (t == 0) g_TICKET = 0;
        }
        if (b == 1 && t <= NG) {
            int lo = 0, hi = NN;
            while (lo < hi) {
                int mid = (lo + hi) >> 1;
                if (__ldg(batch + mid) < t) lo = mid + 1; else hi = mid;
            }
            g_GSTART[t] = lo;
        }
    }
}

// fused: embed (fp16 table gather, blocks [0,WB)) ∥ degree count ---------------
__global__ void __launch_bounds__(256) k_embed_count(const int* __restrict__ seq,
                                                     const int* __restrict__ edge) {
    if (blockIdx.x < WB) {
        int w = blockIdx.x * 8 + (threadIdx.x >> 5);
        int lane = threadIdx.x & 31;
        if (w >= NN) return;
        int tok = (lane < 16) ? seq[w * 16 + lane] : 0;
        const uint4* E = (const uint4*)g_EMBH;
        float acc[8];
#pragma unroll
        for (int q = 0; q < 8; q++) acc[q] = 0.f;
#pragma unroll
        for (int t = 0; t < 16; t++) {
            int tk = __shfl_sync(0xffffffffu, tok, t);
            uint4 v = __ldg(E + tk * 32 + lane);
            float2 f0 = __half22float2(*(__half2*)&v.x);
            float2 f1 = __half22float2(*(__half2*)&v.y);
            float2 f2 = __half22float2(*(__half2*)&v.z);
            float2 f3 = __half22float2(*(__half2*)&v.w);
            acc[0] += f0.x; acc[1] += f0.y;
            acc[2] += f1.x; acc[3] += f1.y;
            acc[4] += f2.x; acc[5] += f2.y;
            acc[6] += f3.x; acc[7] += f3.y;
        }
        union { uint4 u; __half2 h2[4]; } pk;
        pk.h2[0] = __floats2half2_rn(acc[0], acc[1]);
        pk.h2[1] = __floats2half2_rn(acc[2], acc[3]);
        pk.h2[2] = __floats2half2_rn(acc[4], acc[5]);
        pk.h2[3] = __floats2half2_rn(acc[6], acc[7]);
        ((uint4*)g_XH)[w * 32 + lane] = pk.u;
    } else {
        int e = (blockIdx.x - WB) * 256 + threadIdx.x;
        if (e < NE) atomicAdd(&g_DEG[edge[NE + e]], 1);
    }
}

// ---- single-pass decoupled-lookback exclusive scan (+ CPOS, DIS fused) -------
__device__ __forceinline__ int block_scan_incl(int v, int t) {
    __shared__ int ws[8];
    int x = v;
#pragma unroll
    for (int o = 1; o < 32; o <<= 1) {
        int y = __shfl_up_sync(0xffffffffu, x, o);
        if ((t & 31) >= o) x += y;
    }
    if ((t & 31) == 31) ws[t >> 5] = x;
    __syncthreads();
    if (t < 8) {
        int s = ws[t];
#pragma unroll
        for (int o = 1; o < 8; o <<= 1) {
            int y = __shfl_up_sync(0xffu, s, o);
            if (t >= o) s += y;
        }
        ws[t] = s;
    }
    __syncthreads();
    int offs = (t >= 32) ? ws[(t >> 5) - 1] : 0;
    return x + offs;
}

__global__ void __launch_bounds__(256) k_scan() {
    __shared__ int s_bid, s_total, s_prefix;
    int t = threadIdx.x;
    if (t == 0) s_bid = atomicAdd(&g_TICKET, 1);
    __syncthreads();
    int bid = s_bid;
    int i = bid * 256 + t;
    int deg = (i < NN) ? g_DEG[i] : 0;
    int incl = block_scan_incl(deg, t);
    if (t == 255) s_total = incl;
    __syncthreads();
    if (t == 0) {
        int total = s_total;
        if (bid == 0) {
            atomicExch(&g_STATE[0], (2ull << 32) | (unsigned)total);
            s_prefix = 0;
        } else {
            atomicExch(&g_STATE[bid], (1ull << 32) | (unsigned)total);
            int pref = 0;
            int p = bid - 1;
            while (p >= 0) {
                unsigned long long st;
                do { st = atomicAdd(&g_STATE[p], 0ull); } while ((st >> 32) == 0ull);
                pref += (int)(st & 0xffffffffull);
                if ((st >> 32) == 2ull) break;
                p--;
            }
            s_prefix = pref;
            atomicExch(&g_STATE[bid], (2ull << 32) | (unsigned)(pref + total));
        }
    }
    __syncthreads();
    int rp = s_prefix + incl - deg;
    if (i < NN) {
        g_ROWPTR[i] = rp;
        g_CPOS[i] = rp;
        g_DIS[i] = rsqrtf((float)deg + 1.0f);
    }
    if (i == 0) g_ROWPTR[NN] = NE;
}

// ---------------- FP16 tensor-core GEMM ---------------------------------------
#define MMA_F16(d, a, b)                                                       \
    asm volatile(                                                              \
        "mma.sync.aligned.m16n8k16.row.col.f32.f16.f16.f32 "                   \
        "{%0,%1,%2,%3},{%4,%5,%6,%7},{%8,%9},{%0,%1,%2,%3};"                   \
        : "+f"(d[0]), "+f"(d[1]), "+f"(d[2]), "+f"(d[3])                       \
        : "r"(a[0]), "r"(a[1]), "r"(a[2]), "r"(a[3]), "r"(b[0]), "r"(b[1]))

struct __align__(16) GemmSmem {
    __half As[128 * 24];   // [m][k], 24-half row stride
    __half Bs[128 * 24];   // [n][k] (transposed W tile)
};

__device__ __forceinline__ void gemm_body(const float* __restrict__ W,
                                          const float* __restrict__ bias,
                                          int bR, int bC, GemmSmem* sm) {
    int tid = threadIdx.x;
    int warp = tid >> 5, lane = tid & 31;
    int r = lane >> 2, c = lane & 3;
    int wm = (warp >> 2) * 64;
    int wn = (warp & 3) * 32;

    int mA = tid >> 1, kA = (tid & 1) * 8;
    int rowA = bR * 128 + mA;
    int nB = tid & 127, kB = (tid >> 7) * 8;
    const float* Wcol = W + bC * 128 + nB;

    float acc[4][4][4];
#pragma unroll
    for (int i = 0; i < 4; i++)
#pragma unroll
        for (int j = 0; j < 4; j++)
#pragma unroll
            for (int q = 0; q < 4; q++) acc[i][j][q] = 0.f;

    uint4 va = (rowA < NN) ? *(const uint4*)(g_XH + rowA * DD + kA)
                           : make_uint4(0u, 0u, 0u, 0u);
    float fb[8];
#pragma unroll
    for (int j = 0; j < 8; j++) fb[j] = __ldg(Wcol + (kB + j) * DD);

    const uint32_t* A32 = (const uint32_t*)sm->As;
    const uint32_t* B32 = (const uint32_t*)sm->Bs;

    for (int k0 = 0; k0 < DD; k0 += 16) {
        *(uint4*)&sm->As[mA * 24 + kA] = va;
        union { uint4 u; __half2 h2[4]; } pk;
        pk.h2[0] = __floats2half2_rn(fb[0], fb[1]);
        pk.h2[1] = __floats2half2_rn(fb[2], fb[3]);
        pk.h2[2] = __floats2half2_rn(fb[4], fb[5]);
        pk.h2[3] = __floats2half2_rn(fb[6], fb[7]);
        *(uint4*)&sm->Bs[nB * 24 + kB] = pk.u;
        __syncthreads();

        int kn = k0 + 16;
        if (kn < DD) {
            va = (rowA < NN) ? *(const uint4*)(g_XH + rowA * DD + kn + kA)
                             : make_uint4(0u, 0u, 0u, 0u);
#pragma unroll
            for (int j = 0; j < 8; j++) fb[j] = __ldg(Wcol + (kn + kB + j) * DD);
        }

        uint32_t a[4][4], b[4][2];
#pragma unroll
        for (int ti = 0; ti < 4; ti++) {
            int m0 = wm + ti * 16;
            a[ti][0] = A32[(m0 + r) * 12 + c];
            a[ti][1] = A32[(m0 + r + 8) * 12 + c];
            a[ti][2] = A32[(m0 + r) * 12 + c + 4];
            a[ti][3] = A32[(m0 + r + 8) * 12 + c + 4];
        }
#pragma unroll
        for (int tj = 0; tj < 4; tj++) {
            int n0 = wn + tj * 8 + r;
            b[tj][0] = B32[n0 * 12 + c];
            b[tj][1] = B32[n0 * 12 + c + 4];
        }
#pragma unroll
        for (int ti = 0; ti < 4; ti++)
#pragma unroll
            for (int tj = 0; tj < 4; tj++) MMA_F16(acc[ti][tj], a[ti], b[tj]);
        __syncthreads();
    }

#pragma unroll
    for (int ti = 0; ti < 4; ti++) {
        int row0 = bR * 128 + wm + ti * 16 + r;
        int row1 = row0 + 8;
        float dis0 = (row0 < NN) ? g_DIS[row0] : 0.f;
        float dis1 = (row1 < NN) ? g_DIS[row1] : 0.f;
#pragma unroll
        for (int tj = 0; tj < 4; tj++) {
            int col = bC * 128 + wn + tj * 8 + 2 * c;
            float bx = __ldg(bias + col), by = __ldg(bias + col + 1);
            if (row0 < NN) {
                __half2 h = __floats2half2_rn((acc[ti][tj][0] + bx) * dis0,
                                              (acc[ti][tj][1] + by) * dis0);
                *(__half2*)(g_HSH + row0 * DD + col) = h;
            }
            if (row1 < NN) {
                __half2 h = __floats2half2_rn((acc[ti][tj][2] + bx) * dis1,
                                              (acc[ti][tj][3] + by) * dis1);
                *(__half2*)(g_HSH + row1 * DD + col) = h;
            }
        }
    }
}

// fused: layer-1 GEMM (blocks [0,GB)) ∥ CSR fill (blocks [GB,GB+CB))
__global__ void __launch_bounds__(256) k_gemm_fill(const float* __restrict__ W,
                                                   const float* __restrict__ bias,
                                                   const int* __restrict__ edge) {
    __shared__ GemmSmem sm;
    if (blockIdx.x < GB) {
        gemm_body(W, bias, blockIdx.x >> 1, blockIdx.x & 1, &sm);
    } else {
        int e = (blockIdx.x - GB) * 256 + threadIdx.x;
        if (e < NE) {
            int dst = edge[NE + e];
            int p = atomicAdd(&g_CPOS[dst], 1);
            g_CSRC[p] = edge[e];
        }
    }
}

__global__ void __launch_bounds__(256) k_gemm(const float* __restrict__ W,
                                              const float* __restrict__ bias) {
    __shared__ GemmSmem sm;
    gemm_body(W, bias, blockIdx.y, blockIdx.x, &sm);
}

// ---------------- aggregation: warp per node, fp16 rows (512B) ----------------
template <int LAYER1>
__global__ void __launch_bounds__(256) k_agg() {
    int w = (blockIdx.x * blockDim.x + threadIdx.x) >> 5;
    int lane = threadIdx.x & 31;
    if (w >= NN) return;
    int s = g_ROWPTR[w], e = g_ROWPTR[w + 1];
    const uint4* HS = (const uint4*)g_HSH;
    float acc[8];
#pragma unroll
    for (int q = 0; q < 8; q++) acc[q] = 0.f;

    for (int base = s; base < e; base += 32) {
        int cnt = e - base; if (cnt > 32) cnt = 32;
        int mysrc = (lane < cnt) ? g_CSRC[base + lane] : 0;
#pragma unroll 4
        for (int i = 0; i < cnt; i++) {
            int src = __shfl_sync(0xffffffffu, mysrc, i);
            uint4 v = __ldg(HS + src * 32 + lane);
            float2 f0 = __half22float2(*(__half2*)&v.x);
            float2 f1 = __half22float2(*(__half2*)&v.y);
            float2 f2 = __half22float2(*(__half2*)&v.z);
            float2 f3 = __half22float2(*(__half2*)&v.w);
            acc[0] += f0.x; acc[1] += f0.y;
            acc[2] += f1.x; acc[3] += f1.y;
            acc[4] += f2.x; acc[5] += f2.y;
            acc[6] += f3.x; acc[7] += f3.y;
        }
    }
    uint4 sv = __ldg(HS + w * 32 + lane);
    float2 s0 = __half22float2(*(__half2*)&sv.x);
    float2 s1 = __half22float2(*(__half2*)&sv.y);
    float2 s2 = __half22float2(*(__half2*)&sv.z);
    float2 s3 = __half22float2(*(__half2*)&sv.w);
    float dis = g_DIS[w];
    float o[8];
    o[0] = fmaxf(dis * (acc[0] + s0.x), 0.f);
    o[1] = fmaxf(dis * (acc[1] + s0.y), 0.f);
    o[2] = fmaxf(dis * (acc[2] + s1.x), 0.f);
    o[3] = fmaxf(dis * (acc[3] + s1.y), 0.f);
    o[4] = fmaxf(dis * (acc[4] + s2.x), 0.f);
    o[5] = fmaxf(dis * (acc[5] + s2.y), 0.f);
    o[6] = fmaxf(dis * (acc[6] + s3.x), 0.f);
    o[7] = fmaxf(dis * (acc[7] + s3.y), 0.f);
    if (LAYER1) {
        union { uint4 u; __half2 h2[4]; } pk;
        pk.h2[0] = __floats2half2_rn(o[0], o[1]);
        pk.h2[1] = __floats2half2_rn(o[2], o[3]);
        pk.h2[2] = __floats2half2_rn(o[4], o[5]);
        pk.h2[3] = __floats2half2_rn(o[6], o[7]);
        ((uint4*)g_XH)[w * 32 + lane] = pk.u;
    } else {
        float4* OUT4 = (float4*)g_U;
        OUT4[w * 64 + lane * 2 + 0] = make_float4(o[0], o[1], o[2], o[3]);
        OUT4[w * 64 + lane * 2 + 1] = make_float4(o[4], o[5], o[6], o[7]);
    }
}

// pool pass 1: 8 node-chunks per graph -> partial sums
__global__ void k_pool1() {
    int g = blockIdx.x, ch = blockIdx.y;
    int lane = threadIdx.x;
    int s = g_GSTART[g], e = g_GSTART[g + 1];
    int len = e - s;
    int c0 = s + (int)(((long long)len * ch) >> 3);
    int c1 = s + (int)(((long long)len * (ch + 1)) >> 3);
    const float4* U4 = (const float4*)g_U;
    float4 acc = make_float4(0.f, 0.f, 0.f, 0.f);
    for (int n = c0; n < c1; n++) {
        float4 v = __ldg(U4 + n * 64 + lane);
        acc.x += v.x; acc.y += v.y; acc.z += v.z; acc.w += v.w;
    }
    ((float4*)g_PART)[(ch * NG + g) * 64 + lane] = acc;
}

__global__ void k_pool2(float* __restrict__ out) {
    int g = blockIdx.x;
    int lane = threadIdx.x;
    const float4* P4 = (const float4*)g_PART;
    float4 acc = make_float4(0.f, 0.f, 0.f, 0.f);
#pragma unroll
    for (int ch = 0; ch < 8; ch++) {
        float4 v = P4[(ch * NG + g) * 64 + lane];
        acc.x += v.x; acc.y += v.y; acc.z += v.z; acc.w += v.w;
    }
    ((float4*)out)[g * 64 + lane] = acc;
}

// ---------------- launch ------------------------------------------------------

extern "C" void kernel_launch(void* const* d_in, const int* in_sizes, int n_in,
                              void* d_out, int out_size) {
    const int *seq = nullptr, *edge = nullptr, *batch = nullptr;
    const float *emb = nullptr, *W0 = nullptr, *b0 = nullptr, *W1 = nullptr, *b1 = nullptr;
    for (int i = 0; i < n_in; i++) {
        int s = in_sizes[i];
        if (s == NN * 16)            seq  = (const int*)d_in[i];
        else if (s == 2 * NE)        edge = (const int*)d_in[i];
        else if (s == NN)            batch = (const int*)d_in[i];
        else if (s == VOCAB * DD)    emb  = (const float*)d_in[i];
        else if (s == DD * DD) { if (!W0) W0 = (const float*)d_in[i]; else W1 = (const float*)d_in[i]; }
        else if (s == DD)      { if (!b0) b0 = (const float*)d_in[i]; else b1 = (const float*)d_in[i]; }
    }
    float* out = (float*)d_out;

    k_prep<<<VB + SB, 256>>>(batch, emb);
    k_embed_count<<<WB + CB, 256>>>(seq, edge);
    k_scan<<<SB, 256>>>();

    // layer 1 GEMM ∥ CSR fill
    k_gemm_fill<<<GB + CB, 256>>>(W0, b0, edge);
    k_agg<1><<<WB, 256>>>();
    // layer 2
    dim3 gg(2, 391);
    k_gemm<<<gg, 256>>>(W1, b1);
    k_agg<0><<<WB, 256>>>();
    // pool
    dim3 pg(NG, 8);
    k_pool1<<<pg, 64>>>();
    k_pool2<<<NG, 64>>>(out);
}

// round 8
// speedup vs baseline: 3.4011x; 1.0007x over previous
#include <cuda_runtime.h>
#include <cuda_fp16.h>
#include <cstdint>

#define NN 50000
#define NG 64
#define DD 256
#define NE 800000
#define VOCAB 100000

#define WB  6250   // embed warp-blocks: NN/8
#define CB  3125   // edge blocks: NE/256
#define SB  196    // ceil(NN/256)
#define GB  782    // gemm blocks: 2 * 391
#define VB  12500  // emb-convert blocks: VOCAB/8

// ---------------- scratch (device globals: no allocation allowed) -------------
__device__ __half g_EMBH[VOCAB * DD];  // fp16 embedding table (per-call convert)
__device__ __half g_XH[NN * DD];       // layer input fp16
__device__ __half g_HSH[NN * DD];      // h * dis (GEMM out, norm-folded), fp16
__device__ float  g_U[NN * DD];        // layer2 final node feats (fp32 for pool)
__device__ float  g_DIS[NN];           // deg^{-1/2}
__device__ int    g_DEG[NN];
__device__ int    g_ROWPTR[NN + 1];
__device__ int    g_CPOS[NN];
__device__ int    g_CSRC[NE];
__device__ int    g_GSTART[NG + 1];
__device__ float  g_PART[8 * NG * DD];
__device__ unsigned long long g_STATE[SB];
__device__ int    g_TICKET;

// ---------------- prep: emb->fp16 convert ∥ zero deg/state ∥ gstart -----------
__global__ void __launch_bounds__(256) k_prep(const int* __restrict__ batch,
                                              const float* __restrict__ emb) {
    if (blockIdx.x < VB) {
        int row = blockIdx.x * 8 + (threadIdx.x >> 5);
        int lane = threadIdx.x & 31;
        const float4* src = (const float4*)emb + row * 64;
        float4 v0 = __ldg(src + 2 * lane);
        float4 v1 = __ldg(src + 2 * lane + 1);
        union { uint4 u; __half2 h2[4]; } pk;
        pk.h2[0] = __floats2half2_rn(v0.x, v0.y);
        pk.h2[1] = __floats2half2_rn(v0.z, v0.w);
        pk.h2[2] = __floats2half2_rn(v1.x, v1.y);
        pk.h2[3] = __floats2half2_rn(v1.z, v1.w);
        ((uint4*)g_EMBH)[row * 32 + lane] = pk.u;
    } else {
        int b = blockIdx.x - VB;
        int t = threadIdx.x;
        int n = b * 256 + t;
        if (n < NN) g_DEG[n] = 0;
        if (b == 0) {
            if (t < SB) g_STATE[t] = 0ull;
            if (t == 0) g_TICKET = 0;
        }
        if (b == 1 && t <= NG) {
            int lo = 0, hi = NN;
            while (lo < hi) {
                int mid = (lo + hi) >> 1;
                if (__ldg(batch + mid) < t) lo = mid + 1; else hi = mid;
            }
            g_GSTART[t] = lo;
        }
    }
}

// fused: embed (fp16 table gather) ∥ degree count -------------------------------
__global__ void __launch_bounds__(256) k_embed_count(const int* __restrict__ seq,
                                                     const int* __restrict__ edge) {
    if (blockIdx.x < WB) {
        int w = blockIdx.x * 8 + (threadIdx.x >> 5);
        int lane = threadIdx.x & 31;
        if (w >= NN) return;
        int tok = (lane < 16) ? seq[w * 16 + lane] : 0;
        const uint4* E = (const uint4*)g_EMBH;
        float acc[8];
#pragma unroll
        for (int q = 0; q < 8; q++) acc[q] = 0.f;
#pragma unroll
        for (int t = 0; t < 16; t++) {
            int tk = __shfl_sync(0xffffffffu, tok, t);
            uint4 v = __ldg(E + tk * 32 + lane);
            float2 f0 = __half22float2(*(__half2*)&v.x);
            float2 f1 = __half22float2(*(__half2*)&v.y);
            float2 f2 = __half22float2(*(__half2*)&v.z);
            float2 f3 = __half22float2(*(__half2*)&v.w);
            acc[0] += f0.x; acc[1] += f0.y;
            acc[2] += f1.x; acc[3] += f1.y;
            acc[4] += f2.x; acc[5] += f2.y;
            acc[6] += f3.x; acc[7] += f3.y;
        }
        union { uint4 u; __half2 h2[4]; } pk;
        pk.h2[0] = __floats2half2_rn(acc[0], acc[1]);
        pk.h2[1] = __floats2half2_rn(acc[2], acc[3]);
        pk.h2[2] = __floats2half2_rn(acc[4], acc[5]);
        pk.h2[3] = __floats2half2_rn(acc[6], acc[7]);
        ((uint4*)g_XH)[w * 32 + lane] = pk.u;
    } else {
        int e = (blockIdx.x - WB) * 256 + threadIdx.x;
        if (e < NE) atomicAdd(&g_DEG[edge[NE + e]], 1);
    }
}

// ---- single-pass decoupled-lookback exclusive scan (+ CPOS, DIS fused) -------
__device__ __forceinline__ int block_scan_incl(int v, int t) {
    __shared__ int ws[8];
    int x = v;
#pragma unroll
    for (int o = 1; o < 32; o <<= 1) {
        int y = __shfl_up_sync(0xffffffffu, x, o);
        if ((t & 31) >= o) x += y;
    }
    if ((t & 31) == 31) ws[t >> 5] = x;
    __syncthreads();
    if (t < 8) {
        int s = ws[t];
#pragma unroll
        for (int o = 1; o < 8; o <<= 1) {
            int y = __shfl_up_sync(0xffu, s, o);
            if (t >= o) s += y;
        }
        ws[t] = s;
    }
    __syncthreads();
    int offs = (t >= 32) ? ws[(t >> 5) - 1] : 0;
    return x + offs;
}

__global__ void __launch_bounds__(256) k_scan() {
    __shared__ int s_bid, s_total, s_prefix;
    int t = threadIdx.x;
    if (t == 0) s_bid = atomicAdd(&g_TICKET, 1);
    __syncthreads();
    int bid = s_bid;
    int i = bid * 256 + t;
    int deg = (i < NN) ? g_DEG[i] : 0;
    int incl = block_scan_incl(deg, t);
    if (t == 255) s_total = incl;
    __syncthreads();
    if (t == 0) {
        int total = s_total;
        if (bid == 0) {
            atomicExch(&g_STATE[0], (2ull << 32) | (unsigned)total);
            s_prefix = 0;
        } else {
            atomicExch(&g_STATE[bid], (1ull << 32) | (unsigned)total);
            int pref = 0;
            int p = bid - 1;
            while (p >= 0) {
                unsigned long long st;
                do { st = atomicAdd(&g_STATE[p], 0ull); } while ((st >> 32) == 0ull);
                pref += (int)(st & 0xffffffffull);
                if ((st >> 32) == 2ull) break;
                p--;
            }
            s_prefix = pref;
            atomicExch(&g_STATE[bid], (2ull << 32) | (unsigned)(pref + total));
        }
    }
    __syncthreads();
    int rp = s_prefix + incl - deg;
    if (i < NN) {
        g_ROWPTR[i] = rp;
        g_CPOS[i] = rp;
        g_DIS[i] = rsqrtf((float)deg + 1.0f);
    }
    if (i == 0) g_ROWPTR[NN] = NE;
}

// ---------------- FP16 tensor-core GEMM (ldmatrix + double buffer) -------------
#define MMA_F16(d, a, b)                                                       \
    asm volatile(                                                              \
        "mma.sync.aligned.m16n8k16.row.col.f32.f16.f16.f32 "                   \
        "{%0,%1,%2,%3},{%4,%5,%6,%7},{%8,%9},{%0,%1,%2,%3};"                   \
        : "+f"(d[0]), "+f"(d[1]), "+f"(d[2]), "+f"(d[3])                       \
        : "r"(a[0]), "r"(a[1]), "r"(a[2]), "r"(a[3]), "r"(b[0]), "r"(b[1]))

#define LDSM_X4(r0, r1, r2, r3, addr)                                          \
    asm volatile("ldmatrix.sync.aligned.m8n8.x4.shared.b16 {%0,%1,%2,%3}, [%4];" \
                 : "=r"(r0), "=r"(r1), "=r"(r2), "=r"(r3) : "r"(addr))

struct __align__(16) GemmSmem {
    __half As[2][128 * 24];   // [m][k], 24-half row stride
    __half Bs[2][128 * 24];   // [n][k] (transposed W tile)
};

__device__ __forceinline__ uint4 pack8(const float* f) {
    union { uint4 u; __half2 h2[4]; } pk;
    pk.h2[0] = __floats2half2_rn(f[0], f[1]);
    pk.h2[1] = __floats2half2_rn(f[2], f[3]);
    pk.h2[2] = __floats2half2_rn(f[4], f[5]);
    pk.h2[3] = __floats2half2_rn(f[6], f[7]);
    return pk.u;
}

__device__ __forceinline__ void gemm_body(const float* __restrict__ W,
                                          const float* __restrict__ bias,
                                          int bR, int bC, GemmSmem* sm) {
    int tid = threadIdx.x;
    int warp = tid >> 5, lane = tid & 31;
    int r = lane >> 2, c = lane & 3;
    int wm = (warp >> 2) * 64;
    int wn = (warp & 3) * 32;

    int mA = tid >> 1, kA = (tid & 1) * 8;
    int rowA = bR * 128 + mA;
    int nB = tid & 127, kB = (tid >> 7) * 8;
    const float* Wcol = W + bC * 128 + nB;

    // ldmatrix lane addressing (sel = lane>>3, lrow = lane&7)
    int lrow = lane & 7;
    int sel = lane >> 3;
    int aRow = lrow + ((sel & 1) << 3);   // + ti*16 + wm
    int aKof = (sel & 2) ? 8 : 0;
    int bRow = lrow + ((sel >> 1) << 3);  // + tjp*16 + wn
    int bKof = (sel & 1) ? 8 : 0;

    float acc[4][4][4];
#pragma unroll
    for (int i = 0; i < 4; i++)
#pragma unroll
        for (int j = 0; j < 4; j++)
#pragma unroll
            for (int q = 0; q < 4; q++) acc[i][j][q] = 0.f;

    // initial tile (k0 = 0)
    uint4 va = (rowA < NN) ? *(const uint4*)(g_XH + rowA * DD + kA)
                           : make_uint4(0u, 0u, 0u, 0u);
    float fb[8];
#pragma unroll
    for (int j = 0; j < 8; j++) fb[j] = __ldg(Wcol + (kB + j) * DD);
    *(uint4*)&sm->As[0][mA * 24 + kA] = va;
    *(uint4*)&sm->Bs[0][nB * 24 + kB] = pack8(fb);
    __syncthreads();

    int stage = 0;
#pragma unroll 1
    for (int it = 0; it < 16; it++) {
        int kn = (it + 1) * 16;
        uint4 va_n, pb_n;
        if (kn < DD) {
            va_n = (rowA < NN) ? *(const uint4*)(g_XH + rowA * DD + kn + kA)
                               : make_uint4(0u, 0u, 0u, 0u);
            float fbn[8];
#pragma unroll
            for (int j = 0; j < 8; j++) fbn[j] = __ldg(Wcol + (kn + kB + j) * DD);
            pb_n = pack8(fbn);
        }

        uint32_t aBase = (uint32_t)__cvta_generic_to_shared(sm->As[stage]);
        uint32_t bBase = (uint32_t)__cvta_generic_to_shared(sm->Bs[stage]);
        uint32_t a[4][4], b[4][2];
#pragma unroll
        for (int ti = 0; ti < 4; ti++) {
            uint32_t addr = aBase + ((wm + ti * 16 + aRow) * 24 + aKof) * 2;
            LDSM_X4(a[ti][0], a[ti][1], a[ti][2], a[ti][3], addr);
        }
#pragma unroll
        for (int tjp = 0; tjp < 2; tjp++) {
            uint32_t addr = bBase + ((wn + tjp * 16 + bRow) * 24 + bKof) * 2;
            LDSM_X4(b[2 * tjp][0], b[2 * tjp][1], b[2 * tjp + 1][0],
                    b[2 * tjp + 1][1], addr);
        }
#pragma unroll
        for (int ti = 0; ti < 4; ti++)
#pragma unroll
            for (int tj = 0; tj < 4; tj++) MMA_F16(acc[ti][tj], a[ti], b[tj]);

        if (kn < DD) {
            *(uint4*)&sm->As[stage ^ 1][mA * 24 + kA] = va_n;
            *(uint4*)&sm->Bs[stage ^ 1][nB * 24 + kB] = pb_n;
            __syncthreads();
            stage ^= 1;
        }
    }

    // epilogue: HSH = fp16( (acc + bias) * dis[row] )
#pragma unroll
    for (int ti = 0; ti < 4; ti++) {
        int row0 = bR * 128 + wm + ti * 16 + r;
        int row1 = row0 + 8;
        float dis0 = (row0 < NN) ? g_DIS[row0] : 0.f;
        float dis1 = (row1 < NN) ? g_DIS[row1] : 0.f;
#pragma unroll
        for (int tj = 0; tj < 4; tj++) {
            int col = bC * 128 + wn + tj * 8 + 2 * c;
            float bx = __ldg(bias + col), by = __ldg(bias + col + 1);
            if (row0 < NN) {
                __half2 h = __floats2half2_rn((acc[ti][tj][0] + bx) * dis0,
                                              (acc[ti][tj][1] + by) * dis0);
                *(__half2*)(g_HSH + row0 * DD + col) = h;
            }
            if (row1 < NN) {
                __half2 h = __floats2half2_rn((acc[ti][tj][2] + bx) * dis1,
                                              (acc[ti][tj][3] + by) * dis1);
                *(__half2*)(g_HSH + row1 * DD + col) = h;
            }
        }
    }
}

// fused: layer-1 GEMM (blocks [0,GB)) ∥ CSR fill (blocks [GB,GB+CB))
__global__ void __launch_bounds__(256, 2) k_gemm_fill(const float* __restrict__ W,
                                                      const float* __restrict__ bias,
                                                      const int* __restrict__ edge) {
    __shared__ GemmSmem sm;
    if (blockIdx.x < GB) {
        gemm_body(W, bias, blockIdx.x >> 1, blockIdx.x & 1, &sm);
    } else {
        int e = (blockIdx.x - GB) * 256 + threadIdx.x;
        if (e < NE) {
            int dst = edge[NE + e];
            int p = atomicAdd(&g_CPOS[dst], 1);
            g_CSRC[p] = edge[e];
        }
    }
}

__global__ void __launch_bounds__(256, 2) k_gemm(const float* __restrict__ W,
                                                 const float* __restrict__ bias) {
    __shared__ GemmSmem sm;
    gemm_body(W, bias, blockIdx.y, blockIdx.x, &sm);
}

// ---------------- aggregation: warp per node, fp16 rows (512B) ----------------
template <int LAYER1>
__global__ void __launch_bounds__(256) k_agg() {
    int w = (blockIdx.x * blockDim.x + threadIdx.x) >> 5;
    int lane = threadIdx.x & 31;
    if (w >= NN) return;
    int s = g_ROWPTR[w], e = g_ROWPTR[w + 1];
    const uint4* HS = (const uint4*)g_HSH;
    float acc[8];
#pragma unroll
    for (int q = 0; q < 8; q++) acc[q] = 0.f;

    for (int base = s; base < e; base += 32) {
        int cnt = e - base; if (cnt > 32) cnt = 32;
        int mysrc = (lane < cnt) ? g_CSRC[base + lane] : 0;
#pragma unroll 4
        for (int i = 0; i < cnt; i++) {
            int src = __shfl_sync(0xffffffffu, mysrc, i);
            uint4 v = __ldg(HS + src * 32 + lane);
            float2 f0 = __half22float2(*(__half2*)&v.x);
            float2 f1 = __half22float2(*(__half2*)&v.y);
            float2 f2 = __half22float2(*(__half2*)&v.z);
            float2 f3 = __half22float2(*(__half2*)&v.w);
            acc[0] += f0.x; acc[1] += f0.y;
            acc[2] += f1.x; acc[3] += f1.y;
            acc[4] += f2.x; acc[5] += f2.y;
            acc[6] += f3.x; acc[7] += f3.y;
        }
    }
    uint4 sv = __ldg(HS + w * 32 + lane);
    float2 s0 = __half22float2(*(__half2*)&sv.x);
    float2 s1 = __half22float2(*(__half2*)&sv.y);
    float2 s2 = __half22float2(*(__half2*)&sv.z);
    float2 s3 = __half22float2(*(__half2*)&sv.w);
    float dis = g_DIS[w];
    float o[8];
    o[0] = fmaxf(dis * (acc[0] + s0.x), 0.f);
    o[1] = fmaxf(dis * (acc[1] + s0.y), 0.f);
    o[2] = fmaxf(dis * (acc[2] + s1.x), 0.f);
    o[3] = fmaxf(dis * (acc[3] + s1.y), 0.f);
    o[4] = fmaxf(dis * (acc[4] + s2.x), 0.f);
    o[5] = fmaxf(dis * (acc[5] + s2.y), 0.f);
    o[6] = fmaxf(dis * (acc[6] + s3.x), 0.f);
    o[7] = fmaxf(dis * (acc[7] + s3.y), 0.f);
    if (LAYER1) {
        union { uint4 u; __half2 h2[4]; } pk;
        pk.h2[0] = __floats2half2_rn(o[0], o[1]);
        pk.h2[1] = __floats2half2_rn(o[2], o[3]);
        pk.h2[2] = __floats2half2_rn(o[4], o[5]);
        pk.h2[3] = __floats2half2_rn(o[6], o[7]);
        ((uint4*)g_XH)[w * 32 + lane] = pk.u;
    } else {
        float4* OUT4 = (float4*)g_U;
        OUT4[w * 64 + lane * 2 + 0] = make_float4(o[0], o[1], o[2], o[3]);
        OUT4[w * 64 + lane * 2 + 1] = make_float4(o[4], o[5], o[6], o[7]);
    }
}

// pool pass 1: 8 node-chunks per graph -> partial sums
__global__ void k_pool1() {
    int g = blockIdx.x, ch = blockIdx.y;
    int lane = threadIdx.x;
    int s = g_GSTART[g], e = g_GSTART[g + 1];
    int len = e - s;
    int c0 = s + (int)(((long long)len * ch) >> 3);
    int c1 = s + (int)(((long long)len * (ch + 1)) >> 3);
    const float4* U4 = (const float4*)g_U;
    float4 acc = make_float4(0.f, 0.f, 0.f, 0.f);
    for (int n = c0; n < c1; n++) {
        float4 v = __ldg(U4 + n * 64 + lane);
        acc.x += v.x; acc.y += v.y; acc.z += v.z; acc.w += v.w;
    }
    ((float4*)g_PART)[(ch * NG + g) * 64 + lane] = acc;
}

__global__ void k_pool2(float* __restrict__ out) {
    int g = blockIdx.x;
    int lane = threadIdx.x;
    const float4* P4 = (const float4*)g_PART;
    float4 acc = make_float4(0.f, 0.f, 0.f, 0.f);
#pragma unroll
    for (int ch = 0; ch < 8; ch++) {
        float4 v = P4[(ch * NG + g) * 64 + lane];
        acc.x += v.x; acc.y += v.y; acc.z += v.z; acc.w += v.w;
    }
    ((float4*)out)[g * 64 + lane] = acc;
}

// ---------------- launch ------------------------------------------------------

extern "C" void kernel_launch(void* const* d_in, const int* in_sizes, int n_in,
                              void* d_out, int out_size) {
    const int *seq = nullptr, *edge = nullptr, *batch = nullptr;
    const float *emb = nullptr, *W0 = nullptr, *b0 = nullptr, *W1 = nullptr, *b1 = nullptr;
    for (int i = 0; i < n_in; i++) {
        int s = in_sizes[i];
        if (s == NN * 16)            seq  = (const int*)d_in[i];
        else if (s == 2 * NE)        edge = (const int*)d_in[i];
        else if (s == NN)            batch = (const int*)d_in[i];
        else if (s == VOCAB * DD)    emb  = (const float*)d_in[i];
        else if (s == DD * DD) { if (!W0) W0 = (const float*)d_in[i]; else W1 = (const float*)d_in[i]; }
        else if (s == DD)      { if (!b0) b0 = (const float*)d_in[i]; else b1 = (const float*)d_in[i]; }
    }
    float* out = (float*)d_out;

    k_prep<<<VB + SB, 256>>>(batch, emb);
    k_embed_count<<<WB + CB, 256>>>(seq, edge);
    k_scan<<<SB, 256>>>();

    // layer 1 GEMM ∥ CSR fill
    k_gemm_fill<<<GB + CB, 256>>>(W0, b0, edge);
    k_agg<1><<<WB, 256>>>();
    // layer 2
    dim3 gg(2, 391);
    k_gemm<<<gg, 256>>>(W1, b1);
    k_agg<0><<<WB, 256>>>();
    // pool
    dim3 pg(NG, 8);
    k_pool1<<<pg, 64>>>();
    k_pool2<<<NG, 64>>>(out);
}

// round 9
// speedup vs baseline: 3.6279x; 1.0667x over previous
#include <cuda_runtime.h>
#include <cuda_fp16.h>
#include <cstdint>

#define NN 50000
#define NG 64
#define DD 256
#define NE 800000
#define VOCAB 100000

#define WB  6250   // embed warp-blocks: NN/8
#define CB  3125   // edge blocks: NE/256
#define SB  196    // ceil(NN/256)
#define GB  782    // gemm blocks: 2 * 391
#define VB  12500  // emb-convert blocks: VOCAB/8
#define TB  32     // W-transpose blocks (16 per layer)

// ---------------- scratch (device globals: no allocation allowed) -------------
__device__ __half g_EMBH[VOCAB * DD];  // fp16 embedding table (per-call convert)
__device__ __half g_W0T[DD * DD];      // W0 fp16, transposed [n][k]
__device__ __half g_W1T[DD * DD];      // W1 fp16, transposed [n][k]
__device__ __half g_XH[NN * DD];       // layer input fp16
__device__ __half g_HSH[NN * DD];      // h * dis (GEMM out, norm-folded), fp16
__device__ float  g_U[NN * DD];        // layer2 final node feats (fp32 for pool)
__device__ float  g_DIS[NN];           // deg^{-1/2}
__device__ int    g_DEG[NN];
__device__ int    g_ROWPTR[NN + 1];
__device__ int    g_CPOS[NN];
__device__ int    g_CSRC[NE];
__device__ int    g_GSTART[NG + 1];
__device__ float  g_PART[8 * NG * DD];
__device__ unsigned long long g_STATE[SB];
__device__ int    g_TICKET;

// ---------------- prep: emb fp16 ∥ W transpose fp16 ∥ zero ∥ gstart ------------
__global__ void __launch_bounds__(256) k_prep(const int* __restrict__ batch,
                                              const float* __restrict__ emb,
                                              const float* __restrict__ W0,
                                              const float* __restrict__ W1) {
    if (blockIdx.x < VB) {
        int row = blockIdx.x * 8 + (threadIdx.x >> 5);
        int lane = threadIdx.x & 31;
        const float4* src = (const float4*)emb + row * 64;
        float4 v0 = __ldg(src + 2 * lane);
        float4 v1 = __ldg(src + 2 * lane + 1);
        union { uint4 u; __half2 h2[4]; } pk;
        pk.h2[0] = __floats2half2_rn(v0.x, v0.y);
        pk.h2[1] = __floats2half2_rn(v0.z, v0.w);
        pk.h2[2] = __floats2half2_rn(v1.x, v1.y);
        pk.h2[3] = __floats2half2_rn(v1.z, v1.w);
        ((uint4*)g_EMBH)[row * 32 + lane] = pk.u;
        return;
    }
    int b = blockIdx.x - VB;
    int t = threadIdx.x;
    if (b < SB) {
        int n = b * 256 + t;
        if (n < NN) g_DEG[n] = 0;
        if (b == 0) {
            if (t < SB) g_STATE[t] = 0ull;
            if (t == 0) g_TICKET = 0;
        }
        if (b == 1 && t <= NG) {
            int lo = 0, hi = NN;
            while (lo < hi) {
                int mid = (lo + hi) >> 1;
                if (__ldg(batch + mid) < t) lo = mid + 1; else hi = mid;
            }
            g_GSTART[t] = lo;
        }
    } else {
        // W transpose: fp32 [k][n] -> fp16 [n][k]
        int b2 = b - SB;
        const float* Ws = (b2 < 16) ? W0 : W1;
        __half* Wd = (b2 < 16) ? g_W0T : g_W1T;
        int kbase = (b2 & 15) * 16;
#pragma unroll
        for (int p = 0; p < 8; p++) {
            int k = kbase + 2 * p;
            float v0 = __ldg(Ws + k * DD + t);
            float v1 = __ldg(Ws + (k + 1) * DD + t);
            *(__half2*)&Wd[t * DD + k] = __floats2half2_rn(v0, v1);
        }
    }
}

// fused: embed (fp16 table gather) ∥ degree count -------------------------------
__global__ void __launch_bounds__(256) k_embed_count(const int* __restrict__ seq,
                                                     const int* __restrict__ edge) {
    if (blockIdx.x < WB) {
        int w = blockIdx.x * 8 + (threadIdx.x >> 5);
        int lane = threadIdx.x & 31;
        if (w >= NN) return;
        int tok = (lane < 16) ? seq[w * 16 + lane] : 0;
        const uint4* E = (const uint4*)g_EMBH;
        float acc[8];
#pragma unroll
        for (int q = 0; q < 8; q++) acc[q] = 0.f;
#pragma unroll
        for (int t = 0; t < 16; t++) {
            int tk = __shfl_sync(0xffffffffu, tok, t);
            uint4 v = __ldg(E + tk * 32 + lane);
            float2 f0 = __half22float2(*(__half2*)&v.x);
            float2 f1 = __half22float2(*(__half2*)&v.y);
            float2 f2 = __half22float2(*(__half2*)&v.z);
            float2 f3 = __half22float2(*(__half2*)&v.w);
            acc[0] += f0.x; acc[1] += f0.y;
            acc[2] += f1.x; acc[3] += f1.y;
            acc[4] += f2.x; acc[5] += f2.y;
            acc[6] += f3.x; acc[7] += f3.y;
        }
        union { uint4 u; __half2 h2[4]; } pk;
        pk.h2[0] = __floats2half2_rn(acc[0], acc[1]);
        pk.h2[1] = __floats2half2_rn(acc[2], acc[3]);
        pk.h2[2] = __floats2half2_rn(acc[4], acc[5]);
        pk.h2[3] = __floats2half2_rn(acc[6], acc[7]);
        ((uint4*)g_XH)[w * 32 + lane] = pk.u;
    } else {
        int e = (blockIdx.x - WB) * 256 + threadIdx.x;
        if (e < NE) atomicAdd(&g_DEG[edge[NE + e]], 1);
    }
}

// ---- single-pass decoupled-lookback exclusive scan (+ CPOS, DIS fused) -------
__device__ __forceinline__ int block_scan_incl(int v, int t) {
    __shared__ int ws[8];
    int x = v;
#pragma unroll
    for (int o = 1; o < 32; o <<= 1) {
        int y = __shfl_up_sync(0xffffffffu, x, o);
        if ((t & 31) >= o) x += y;
    }
    if ((t & 31) == 31) ws[t >> 5] = x;
    __syncthreads();
    if (t < 8) {
        int s = ws[t];
#pragma unroll
        for (int o = 1; o < 8; o <<= 1) {
            int y = __shfl_up_sync(0xffu, s, o);
            if (t >= o) s += y;
        }
        ws[t] = s;
    }
    __syncthreads();
    int offs = (t >= 32) ? ws[(t >> 5) - 1] : 0;
    return x + offs;
}

__global__ void __launch_bounds__(256) k_scan() {
    __shared__ int s_bid, s_total, s_prefix;
    int t = threadIdx.x;
    if (t == 0) s_bid = atomicAdd(&g_TICKET, 1);
    __syncthreads();
    int bid = s_bid;
    int i = bid * 256 + t;
    int deg = (i < NN) ? g_DEG[i] : 0;
    int incl = block_scan_incl(deg, t);
    if (t == 255) s_total = incl;
    __syncthreads();
    if (t == 0) {
        int total = s_total;
        if (bid == 0) {
            atomicExch(&g_STATE[0], (2ull << 32) | (unsigned)total);
            s_prefix = 0;
        } else {
            atomicExch(&g_STATE[bid], (1ull << 32) | (unsigned)total);
            int pref = 0;
            int p = bid - 1;
            while (p >= 0) {
                unsigned long long st;
                do { st = atomicAdd(&g_STATE[p], 0ull); } while ((st >> 32) == 0ull);
                pref += (int)(st & 0xffffffffull);
                if ((st >> 32) == 2ull) break;
                p--;
            }
            s_prefix = pref;
            atomicExch(&g_STATE[bid], (2ull << 32) | (unsigned)(pref + total));
        }
    }
    __syncthreads();
    int rp = s_prefix + incl - deg;
    if (i < NN) {
        g_ROWPTR[i] = rp;
        g_CPOS[i] = rp;
        g_DIS[i] = rsqrtf((float)deg + 1.0f);
    }
    if (i == 0) g_ROWPTR[NN] = NE;
}

// ---------------- FP16 tensor-core GEMM (cp.async 3-stage, BK=32) --------------
#define MMA_F16S(d, a0, a1, a2, a3, b0, b1)                                    \
    asm volatile(                                                              \
        "mma.sync.aligned.m16n8k16.row.col.f32.f16.f16.f32 "                   \
        "{%0,%1,%2,%3},{%4,%5,%6,%7},{%8,%9},{%0,%1,%2,%3};"                   \
        : "+f"(d[0]), "+f"(d[1]), "+f"(d[2]), "+f"(d[3])                       \
        : "r"(a0), "r"(a1), "r"(a2), "r"(a3), "r"(b0), "r"(b1))

#define LDSM_X4(r0, r1, r2, r3, addr)                                          \
    asm volatile("ldmatrix.sync.aligned.m8n8.x4.shared.b16 {%0,%1,%2,%3}, [%4];" \
                 : "=r"(r0), "=r"(r1), "=r"(r2), "=r"(r3) : "r"(addr))

#define CP16(saddr, gptr)                                                      \
    asm volatile("cp.async.ca.shared.global [%0], [%1], 16;"                   \
                 :: "r"(saddr), "l"(gptr))
#define CP_COMMIT() asm volatile("cp.async.commit_group;")

#define RSTR 40  // smem row stride in halves (conflict-free, 16B-aligned)

struct __align__(16) GemmSmem {
    __half As[3][128 * RSTR];
    __half Bs[3][128 * RSTR];
};

__device__ __forceinline__ void gemm_body(const __half* __restrict__ WT,
                                          const float* __restrict__ bias,
                                          int bR, int bC, GemmSmem* sm) {
    int tid = threadIdx.x;
    int warp = tid >> 5, lane = tid & 31;
    int r = lane >> 2, c = lane & 3;
    int wm = (warp >> 2) * 64;
    int wn = (warp & 3) * 32;

    // per-thread cp.async slots: row idx 0..127, k-half offset 0 or 16
    int mrow = tid >> 1;
    int kh = (tid & 1) * 16;
    int rowA = bR * 128 + mrow;
    int rowAc = rowA < NN ? rowA : NN - 1;  // clamp (epilogue guards real rows)
    const __half* gA = g_XH + rowAc * DD + kh;
    const __half* gB = WT + (bC * 128 + mrow) * DD + kh;

    // ldmatrix lane addressing
    int lrow = lane & 7;
    int sel = lane >> 3;
    int aRow = lrow + ((sel & 1) << 3);
    int aKof = (sel & 2) ? 8 : 0;
    int bRow = lrow + ((sel >> 1) << 3);
    int bKof = (sel & 1) ? 8 : 0;

    float acc[4][4][4];
#pragma unroll
    for (int i = 0; i < 4; i++)
#pragma unroll
        for (int j = 0; j < 4; j++)
#pragma unroll
            for (int q = 0; q < 4; q++) acc[i][j][q] = 0.f;

    uint32_t sA0 = (uint32_t)__cvta_generic_to_shared(&sm->As[0][0]);
    uint32_t sB0 = (uint32_t)__cvta_generic_to_shared(&sm->Bs[0][0]);
    const uint32_t STG_B = 128 * RSTR * 2;  // stage stride bytes
    uint32_t dOffA = (mrow * RSTR + kh) * 2;
    uint32_t dOffB = (mrow * RSTR + kh) * 2;

    // prologue: tiles 0,1
#pragma unroll
    for (int pt = 0; pt < 2; pt++) {
        uint32_t dA = sA0 + pt * STG_B + dOffA;
        uint32_t dB = sB0 + pt * STG_B + dOffB;
        CP16(dA, gA + pt * 32); CP16(dA + 16, gA + pt * 32 + 8);
        CP16(dB, gB + pt * 32); CP16(dB + 16, gB + pt * 32 + 8);
        CP_COMMIT();
    }

#pragma unroll 1
    for (int it = 0; it < 8; it++) {
        if (it < 7) asm volatile("cp.async.wait_group 1;");
        else        asm volatile("cp.async.wait_group 0;");
        __syncthreads();

        if (it + 2 < 8) {
            int st = (it + 2) % 3;
            int kt = (it + 2) * 32;
            uint32_t dA = sA0 + st * STG_B + dOffA;
            uint32_t dB = sB0 + st * STG_B + dOffB;
            CP16(dA, gA + kt); CP16(dA + 16, gA + kt + 8);
            CP16(dB, gB + kt); CP16(dB + 16, gB + kt + 8);
            CP_COMMIT();
        }

        int cur = it % 3;
        uint32_t aBase = sA0 + cur * STG_B;
        uint32_t bBase = sB0 + cur * STG_B;
#pragma unroll
        for (int kc = 0; kc < 2; kc++) {
            uint32_t a[4][4], bb[2][4];
#pragma unroll
            for (int ti = 0; ti < 4; ti++) {
                uint32_t addr = aBase + ((wm + ti * 16 + aRow) * RSTR + kc * 16 + aKof) * 2;
                LDSM_X4(a[ti][0], a[ti][1], a[ti][2], a[ti][3], addr);
            }
#pragma unroll
            for (int tjp = 0; tjp < 2; tjp++) {
                uint32_t addr = bBase + ((wn + tjp * 16 + bRow) * RSTR + kc * 16 + bKof) * 2;
                LDSM_X4(bb[tjp][0], bb[tjp][1], bb[tjp][2], bb[tjp][3], addr);
            }
#pragma unroll
            for (int ti = 0; ti < 4; ti++) {
#pragma unroll
                for (int tjp = 0; tjp < 2; tjp++) {
                    MMA_F16S(acc[ti][2 * tjp], a[ti][0], a[ti][1], a[ti][2], a[ti][3],
                             bb[tjp][0], bb[tjp][1]);
                    MMA_F16S(acc[ti][2 * tjp + 1], a[ti][0], a[ti][1], a[ti][2], a[ti][3],
                             bb[tjp][2], bb[tjp][3]);
                }
            }
        }
    }

    // epilogue: HSH = fp16( (acc + bias) * dis[row] )
#pragma unroll
    for (int ti = 0; ti < 4; ti++) {
        int row0 = bR * 128 + wm + ti * 16 + r;
        int row1 = row0 + 8;
        float dis0 = (row0 < NN) ? g_DIS[row0] : 0.f;
        float dis1 = (row1 < NN) ? g_DIS[row1] : 0.f;
#pragma unroll
        for (int tj = 0; tj < 4; tj++) {
            int col = bC * 128 + wn + tj * 8 + 2 * c;
            float bx = __ldg(bias + col), by = __ldg(bias + col + 1);
            if (row0 < NN) {
                __half2 h = __floats2half2_rn((acc[ti][tj][0] + bx) * dis0,
                                              (acc[ti][tj][1] + by) * dis0);
                *(__half2*)(g_HSH + row0 * DD + col) = h;
            }
            if (row1 < NN) {
                __half2 h = __floats2half2_rn((acc[ti][tj][2] + bx) * dis1,
                                              (acc[ti][tj][3] + by) * dis1);
                *(__half2*)(g_HSH + row1 * DD + col) = h;
            }
        }
    }
}

// fused: layer-1 GEMM (blocks [0,GB)) ∥ CSR fill (blocks [GB,GB+CB))
__global__ void __launch_bounds__(256, 2) k_gemm_fill(const float* __restrict__ bias,
                                                      const int* __restrict__ edge) {
    __shared__ GemmSmem sm;
    if (blockIdx.x < GB) {
        gemm_body(g_W0T, bias, blockIdx.x >> 1, blockIdx.x & 1, &sm);
    } else {
        int e = (blockIdx.x - GB) * 256 + threadIdx.x;
        if (e < NE) {
            int dst = edge[NE + e];
            int p = atomicAdd(&g_CPOS[dst], 1);
            g_CSRC[p] = edge[e];
        }
    }
}

__global__ void __launch_bounds__(256, 2) k_gemm(const float* __restrict__ bias) {
    __shared__ GemmSmem sm;
    gemm_body(g_W1T, bias, blockIdx.y, blockIdx.x, &sm);
}

// ---------------- aggregation: warp per node, fp16 rows (512B) ----------------
template <int LAYER1>
__global__ void __launch_bounds__(256) k_agg() {
    int w = (blockIdx.x * blockDim.x + threadIdx.x) >> 5;
    int lane = threadIdx.x & 31;
    if (w >= NN) return;
    int s = g_ROWPTR[w], e = g_ROWPTR[w + 1];
    const uint4* HS = (const uint4*)g_HSH;
    float acc[8];
#pragma unroll
    for (int q = 0; q < 8; q++) acc[q] = 0.f;

    for (int base = s; base < e; base += 32) {
        int cnt = e - base; if (cnt > 32) cnt = 32;
        int mysrc = (lane < cnt) ? g_CSRC[base + lane] : 0;
#pragma unroll 4
        for (int i = 0; i < cnt; i++) {
            int src = __shfl_sync(0xffffffffu, mysrc, i);
            uint4 v = __ldg(HS + src * 32 + lane);
            float2 f0 = __half22float2(*(__half2*)&v.x);
            float2 f1 = __half22float2(*(__half2*)&v.y);
            float2 f2 = __half22float2(*(__half2*)&v.z);
            float2 f3 = __half22float2(*(__half2*)&v.w);
            acc[0] += f0.x; acc[1] += f0.y;
            acc[2] += f1.x; acc[3] += f1.y;
            acc[4] += f2.x; acc[5] += f2.y;
            acc[6] += f3.x; acc[7] += f3.y;
        }
    }
    uint4 sv = __ldg(HS + w * 32 + lane);
    float2 s0 = __half22float2(*(__half2*)&sv.x);
    float2 s1 = __half22float2(*(__half2*)&sv.y);
    float2 s2 = __half22float2(*(__half2*)&sv.z);
    float2 s3 = __half22float2(*(__half2*)&sv.w);
    float dis = g_DIS[w];
    float o[8];
    o[0] = fmaxf(dis * (acc[0] + s0.x), 0.f);
    o[1] = fmaxf(dis * (acc[1] + s0.y), 0.f);
    o[2] = fmaxf(dis * (acc[2] + s1.x), 0.f);
    o[3] = fmaxf(dis * (acc[3] + s1.y), 0.f);
    o[4] = fmaxf(dis * (acc[4] + s2.x), 0.f);
    o[5] = fmaxf(dis * (acc[5] + s2.y), 0.f);
    o[6] = fmaxf(dis * (acc[6] + s3.x), 0.f);
    o[7] = fmaxf(dis * (acc[7] + s3.y), 0.f);
    if (LAYER1) {
        union { uint4 u; __half2 h2[4]; } pk;
        pk.h2[0] = __floats2half2_rn(o[0], o[1]);
        pk.h2[1] = __floats2half2_rn(o[2], o[3]);
        pk.h2[2] = __floats2half2_rn(o[4], o[5]);
        pk.h2[3] = __floats2half2_rn(o[6], o[7]);
        ((uint4*)g_XH)[w * 32 + lane] = pk.u;
    } else {
        float4* OUT4 = (float4*)g_U;
        OUT4[w * 64 + lane * 2 + 0] = make_float4(o[0], o[1], o[2], o[3]);
        OUT4[w * 64 + lane * 2 + 1] = make_float4(o[4], o[5], o[6], o[7]);
    }
}

// pool pass 1: 8 node-chunks per graph -> partial sums
__global__ void k_pool1() {
    int g = blockIdx.x, ch = blockIdx.y;
    int lane = threadIdx.x;
    int s = g_GSTART[g], e = g_GSTART[g + 1];
    int len = e - s;
    int c0 = s + (int)(((long long)len * ch) >> 3);
    int c1 = s + (int)(((long long)len * (ch + 1)) >> 3);
    const float4* U4 = (const float4*)g_U;
    float4 acc = make_float4(0.f, 0.f, 0.f, 0.f);
    for (int n = c0; n < c1; n++) {
        float4 v = __ldg(U4 + n * 64 + lane);
        acc.x += v.x; acc.y += v.y; acc.z += v.z; acc.w += v.w;
    }
    ((float4*)g_PART)[(ch * NG + g) * 64 + lane] = acc;
}

__global__ void k_pool2(float* __restrict__ out) {
    int g = blockIdx.x;
    int lane = threadIdx.x;
    const float4* P4 = (const float4*)g_PART;
    float4 acc = make_float4(0.f, 0.f, 0.f, 0.f);
#pragma unroll
    for (int ch = 0; ch < 8; ch++) {
        float4 v = P4[(ch * NG + g) * 64 + lane];
        acc.x += v.x; acc.y += v.y; acc.z += v.z; acc.w += v.w;
    }
    ((float4*)out)[g * 64 + lane] = acc;
}

// ---------------- launch ------------------------------------------------------

extern "C" void kernel_launch(void* const* d_in, const int* in_sizes, int n_in,
                              void* d_out, int out_size) {
    const int *seq = nullptr, *edge = nullptr, *batch = nullptr;
    const float *emb = nullptr, *W0 = nullptr, *b0 = nullptr, *W1 = nullptr, *b1 = nullptr;
    for (int i = 0; i < n_in; i++) {
        int s = in_sizes[i];
        if (s == NN * 16)            seq  = (const int*)d_in[i];
        else if (s == 2 * NE)        edge = (const int*)d_in[i];
        else if (s == NN)            batch = (const int*)d_in[i];
        else if (s == VOCAB * DD)    emb  = (const float*)d_in[i];
        else if (s == DD * DD) { if (!W0) W0 = (const float*)d_in[i]; else W1 = (const float*)d_in[i]; }
        else if (s == DD)      { if (!b0) b0 = (const float*)d_in[i]; else b1 = (const float*)d_in[i]; }
    }
    float* out = (float*)d_out;

    k_prep<<<VB + SB + TB, 256>>>(batch, emb, W0, W1);
    k_embed_count<<<WB + CB, 256>>>(seq, edge);
    k_scan<<<SB, 256>>>();

    // layer 1 GEMM ∥ CSR fill
    k_gemm_fill<<<GB + CB, 256>>>(b0, edge);
    k_agg<1><<<WB, 256>>>();
    // layer 2
    dim3 gg(2, 391);
    k_gemm<<<gg, 256>>>(b1);
    k_agg<0><<<WB, 256>>>();
    // pool
    dim3 pg(NG, 8);
    k_pool1<<<pg, 64>>>();
    k_pool2<<<NG, 64>>>(out);
}

// round 10
// speedup vs baseline: 3.6511x; 1.0064x over previous
#include <cuda_runtime.h>
#include <cuda_fp16.h>
#include <cstdint>

#define NN 50000
#define NG 64
#define DD 256
#define NE 800000
#define VOCAB 100000

#define WB  6250   // embed warp-blocks: NN/8
#define CB  3125   // edge blocks: NE/256
#define SB  196    // ceil(NN/256)
#define VB  12500  // emb-convert blocks: VOCAB/8
#define TB  32     // W-transpose blocks (16 per layer)
#define PG  296    // persistent gemm CTAs (2 per SM x 148)
#define NRT 391    // row tiles: ceil(NN/128)

// ---------------- scratch (device globals: no allocation allowed) -------------
__device__ __half g_EMBH[VOCAB * DD];  // fp16 embedding table (per-call convert)
__device__ __half g_W0T[DD * DD];      // W0 fp16, transposed [n][k]
__device__ __half g_W1T[DD * DD];      // W1 fp16, transposed [n][k]
__device__ __half g_XH[NN * DD];       // layer input fp16
__device__ __half g_HSH[NN * DD];      // h * dis (GEMM out, norm-folded), fp16
__device__ float  g_U[NN * DD];        // layer2 final node feats (fp32 for pool)
__device__ float  g_DIS[NN];           // deg^{-1/2}
__device__ int    g_DEG[NN];
__device__ int    g_ROWPTR[NN + 1];
__device__ int    g_CPOS[NN];
__device__ int    g_CSRC[NE];
__device__ int    g_GSTART[NG + 1];
__device__ float  g_PART[8 * NG * DD];
__device__ unsigned long long g_STATE[SB];
__device__ int    g_TICKET;

// ---------------- prep: emb fp16 ∥ W transpose fp16 ∥ zero ∥ gstart ------------
__global__ void __launch_bounds__(256) k_prep(const int* __restrict__ batch,
                                              const float* __restrict__ emb,
                                              const float* __restrict__ W0,
                                              const float* __restrict__ W1) {
    if (blockIdx.x < VB) {
        int row = blockIdx.x * 8 + (threadIdx.x >> 5);
        int lane = threadIdx.x & 31;
        const float4* src = (const float4*)emb + row * 64;
        float4 v0 = __ldg(src + 2 * lane);
        float4 v1 = __ldg(src + 2 * lane + 1);
        union { uint4 u; __half2 h2[4]; } pk;
        pk.h2[0] = __floats2half2_rn(v0.x, v0.y);
        pk.h2[1] = __floats2half2_rn(v0.z, v0.w);
        pk.h2[2] = __floats2half2_rn(v1.x, v1.y);
        pk.h2[3] = __floats2half2_rn(v1.z, v1.w);
        ((uint4*)g_EMBH)[row * 32 + lane] = pk.u;
        return;
    }
    int b = blockIdx.x - VB;
    int t = threadIdx.x;
    if (b < SB) {
        int n = b * 256 + t;
        if (n < NN) g_DEG[n] = 0;
        if (b == 0) {
            if (t < SB) g_STATE[t] = 0ull;
            if (t == 0) g_TICKET = 0;
        }
        if (b == 1 && t <= NG) {
            int lo = 0, hi = NN;
            while (lo < hi) {
                int mid = (lo + hi) >> 1;
                if (__ldg(batch + mid) < t) lo = mid + 1; else hi = mid;
            }
            g_GSTART[t] = lo;
        }
    } else {
        // W transpose: fp32 [k][n] -> fp16 [n][k]
        int b2 = b - SB;
        const float* Ws = (b2 < 16) ? W0 : W1;
        __half* Wd = (b2 < 16) ? g_W0T : g_W1T;
        int kbase = (b2 & 15) * 16;
#pragma unroll
        for (int p = 0; p < 8; p++) {
            int k = kbase + 2 * p;
            float v0 = __ldg(Ws + k * DD + t);
            float v1 = __ldg(Ws + (k + 1) * DD + t);
            *(__half2*)&Wd[t * DD + k] = __floats2half2_rn(v0, v1);
        }
    }
}

// fused: embed (fp16 table gather) ∥ degree count -------------------------------
__global__ void __launch_bounds__(256) k_embed_count(const int* __restrict__ seq,
                                                     const int* __restrict__ edge) {
    if (blockIdx.x < WB) {
        int w = blockIdx.x * 8 + (threadIdx.x >> 5);
        int lane = threadIdx.x & 31;
        if (w >= NN) return;
        int tok = (lane < 16) ? seq[w * 16 + lane] : 0;
        const uint4* E = (const uint4*)g_EMBH;
        float acc[8];
#pragma unroll
        for (int q = 0; q < 8; q++) acc[q] = 0.f;
#pragma unroll
        for (int t = 0; t < 16; t++) {
            int tk = __shfl_sync(0xffffffffu, tok, t);
            uint4 v = __ldg(E + tk * 32 + lane);
            float2 f0 = __half22float2(*(__half2*)&v.x);
            float2 f1 = __half22float2(*(__half2*)&v.y);
            float2 f2 = __half22float2(*(__half2*)&v.z);
            float2 f3 = __half22float2(*(__half2*)&v.w);
            acc[0] += f0.x; acc[1] += f0.y;
            acc[2] += f1.x; acc[3] += f1.y;
            acc[4] += f2.x; acc[5] += f2.y;
            acc[6] += f3.x; acc[7] += f3.y;
        }
        union { uint4 u; __half2 h2[4]; } pk;
        pk.h2[0] = __floats2half2_rn(acc[0], acc[1]);
        pk.h2[1] = __floats2half2_rn(acc[2], acc[3]);
        pk.h2[2] = __floats2half2_rn(acc[4], acc[5]);
        pk.h2[3] = __floats2half2_rn(acc[6], acc[7]);
        ((uint4*)g_XH)[w * 32 + lane] = pk.u;
    } else {
        int e = (blockIdx.x - WB) * 256 + threadIdx.x;
        if (e < NE) atomicAdd(&g_DEG[edge[NE + e]], 1);
    }
}

// ---- single-pass decoupled-lookback exclusive scan (+ CPOS, DIS fused) -------
__device__ __forceinline__ int block_scan_incl(int v, int t) {
    __shared__ int ws[8];
    int x = v;
#pragma unroll
    for (int o = 1; o < 32; o <<= 1) {
        int y = __shfl_up_sync(0xffffffffu, x, o);
        if ((t & 31) >= o) x += y;
    }
    if ((t & 31) == 31) ws[t >> 5] = x;
    __syncthreads();
    if (t < 8) {
        int s = ws[t];
#pragma unroll
        for (int o = 1; o < 8; o <<= 1) {
            int y = __shfl_up_sync(0xffu, s, o);
            if (t >= o) s += y;
        }
        ws[t] = s;
    }
    __syncthreads();
    int offs = (t >= 32) ? ws[(t >> 5) - 1] : 0;
    return x + offs;
}

__global__ void __launch_bounds__(256) k_scan() {
    __shared__ int s_bid, s_total, s_prefix;
    int t = threadIdx.x;
    if (t == 0) s_bid = atomicAdd(&g_TICKET, 1);
    __syncthreads();
    int bid = s_bid;
    int i = bid * 256 + t;
    int deg = (i < NN) ? g_DEG[i] : 0;
    int incl = block_scan_incl(deg, t);
    if (t == 255) s_total = incl;
    __syncthreads();
    if (t == 0) {
        int total = s_total;
        if (bid == 0) {
            atomicExch(&g_STATE[0], (2ull << 32) | (unsigned)total);
            s_prefix = 0;
        } else {
            atomicExch(&g_STATE[bid], (1ull << 32) | (unsigned)total);
            int pref = 0;
            int p = bid - 1;
            while (p >= 0) {
                unsigned long long st;
                do { st = atomicAdd(&g_STATE[p], 0ull); } while ((st >> 32) == 0ull);
                pref += (int)(st & 0xffffffffull);
                if ((st >> 32) == 2ull) break;
                p--;
            }
            s_prefix = pref;
            atomicExch(&g_STATE[bid], (2ull << 32) | (unsigned)(pref + total));
        }
    }
    __syncthreads();
    int rp = s_prefix + incl - deg;
    if (i < NN) {
        g_ROWPTR[i] = rp;
        g_CPOS[i] = rp;
        g_DIS[i] = rsqrtf((float)deg + 1.0f);
    }
    if (i == 0) g_ROWPTR[NN] = NE;
}

// ---------- persistent FP16 GEMM: W resident in smem, A cp.async 3-stage ------
#define MMA_F16S(d, a0, a1, a2, a3, b0, b1)                                    \
    asm volatile(                                                              \
        "mma.sync.aligned.m16n8k16.row.col.f32.f16.f16.f32 "                   \
        "{%0,%1,%2,%3},{%4,%5,%6,%7},{%8,%9},{%0,%1,%2,%3};"                   \
        : "+f"(d[0]), "+f"(d[1]), "+f"(d[2]), "+f"(d[3])                       \
        : "r"(a0), "r"(a1), "r"(a2), "r"(a3), "r"(b0), "r"(b1))

#define LDSM_X4(r0, r1, r2, r3, addr)                                          \
    asm volatile("ldmatrix.sync.aligned.m8n8.x4.shared.b16 {%0,%1,%2,%3}, [%4];" \
                 : "=r"(r0), "=r"(r1), "=r"(r2), "=r"(r3) : "r"(addr))

#define CP16(saddr, gptr)                                                      \
    asm volatile("cp.async.ca.shared.global [%0], [%1], 16;"                   \
                 :: "r"(saddr), "l"(gptr))
#define CP_COMMIT() asm volatile("cp.async.commit_group;")

#define ASTR 40   // A smem row stride (halves) — conflict-free for ldmatrix
#define WSTR 264  // W smem row stride (halves) — 528B ≡ 16 mod 128: conflict-free

struct __align__(16) GemmPSmem {
    __half Ws[128 * WSTR];    // 67584 B — resident W column tile [n][k]
    __half As[3][128 * ASTR]; // 3 x 10240 B
};

template <int FILL>
__global__ void __launch_bounds__(256, 2) k_gemm_p(const __half* __restrict__ WT,
                                                   const float* __restrict__ bias,
                                                   const int* __restrict__ edge) {
    __shared__ GemmPSmem sm;
    int cid = blockIdx.x;
    int bC = cid & 1;
    int crow = cid >> 1;       // 0..147
    int tid = threadIdx.x;
    int warp = tid >> 5, lane = tid & 31;
    int r = lane >> 2, c = lane & 3;
    int wm = (warp >> 2) * 64;
    int wn = (warp & 3) * 32;

    // ---- issue W load (one cp.async group, overlapped with fill below) ----
    uint32_t wBase = (uint32_t)__cvta_generic_to_shared(sm.Ws);
    const __half* gW = WT + bC * 128 * DD;
#pragma unroll
    for (int i = 0; i < 16; i++) {
        int ch = tid + i * 256;
        int row = ch >> 5;
        int ko = (ch & 31) * 8;
        CP16(wBase + (row * WSTR + ko) * 2, gW + row * DD + ko);
    }
    CP_COMMIT();

    // ---- CSR fill slice (only layer-1) ----
    if (FILL) {
        const int per = (NE + PG - 1) / PG;  // 2703
        int e0 = cid * per;
        int e1 = e0 + per; if (e1 > NE) e1 = NE;
        for (int e = e0 + tid; e < e1; e += 256) {
            int dst = edge[NE + e];
            int p = atomicAdd(&g_CPOS[dst], 1);
            g_CSRC[p] = edge[e];
        }
    }

    asm volatile("cp.async.wait_group 0;");
    __syncthreads();

    // ldmatrix lane addressing
    int lrow = lane & 7;
    int sel = lane >> 3;
    int aRow = lrow + ((sel & 1) << 3);
    int aKof = (sel & 2) ? 8 : 0;
    int bRow = lrow + ((sel >> 1) << 3);
    int bKof = (sel & 1) ? 8 : 0;

    uint32_t sA0 = (uint32_t)__cvta_generic_to_shared(&sm.As[0][0]);
    const uint32_t STG_B = 128 * ASTR * 2;
    int mrow = tid >> 1;
    int kh = (tid & 1) * 16;
    uint32_t dOffA = (mrow * ASTR + kh) * 2;

    // ---- loop over assigned row tiles ----
    for (int bR = crow; bR < NRT; bR += 148) {
        int rowA = bR * 128 + mrow;
        int rowAc = rowA < NN ? rowA : NN - 1;
        const __half* gA = g_XH + rowAc * DD + kh;

        float acc[4][4][4];
#pragma unroll
        for (int i = 0; i < 4; i++)
#pragma unroll
            for (int j = 0; j < 4; j++)
#pragma unroll
                for (int q = 0; q < 4; q++) acc[i][j][q] = 0.f;

        // prologue: A k-tiles 0,1
#pragma unroll
        for (int pt = 0; pt < 2; pt++) {
            uint32_t dA = sA0 + pt * STG_B + dOffA;
            CP16(dA, gA + pt * 32); CP16(dA + 16, gA + pt * 32 + 8);
            CP_COMMIT();
        }

#pragma unroll 1
        for (int it = 0; it < 8; it++) {
            if (it < 7) asm volatile("cp.async.wait_group 1;");
            else        asm volatile("cp.async.wait_group 0;");
            __syncthreads();

            if (it + 2 < 8) {
                int st = (it + 2) % 3;
                uint32_t dA = sA0 + st * STG_B + dOffA;
                CP16(dA, gA + (it + 2) * 32); CP16(dA + 16, gA + (it + 2) * 32 + 8);
                CP_COMMIT();
            }

            uint32_t aBase = sA0 + (it % 3) * STG_B;
#pragma unroll
            for (int kc = 0; kc < 2; kc++) {
                int k0 = it * 32 + kc * 16;
                uint32_t a[4][4], bb[2][4];
#pragma unroll
                for (int ti = 0; ti < 4; ti++) {
                    uint32_t addr = aBase + ((wm + ti * 16 + aRow) * ASTR + kc * 16 + aKof) * 2;
                    LDSM_X4(a[ti][0], a[ti][1], a[ti][2], a[ti][3], addr);
                }
#pragma unroll
                for (int tjp = 0; tjp < 2; tjp++) {
                    uint32_t addr = wBase + ((wn + tjp * 16 + bRow) * WSTR + k0 + bKof) * 2;
                    LDSM_X4(bb[tjp][0], bb[tjp][1], bb[tjp][2], bb[tjp][3], addr);
                }
#pragma unroll
                for (int ti = 0; ti < 4; ti++) {
#pragma unroll
                    for (int tjp = 0; tjp < 2; tjp++) {
                        MMA_F16S(acc[ti][2 * tjp], a[ti][0], a[ti][1], a[ti][2], a[ti][3],
                                 bb[tjp][0], bb[tjp][1]);
                        MMA_F16S(acc[ti][2 * tjp + 1], a[ti][0], a[ti][1], a[ti][2], a[ti][3],
                                 bb[tjp][2], bb[tjp][3]);
                    }
                }
            }
        }
        __syncthreads();  // protect A stages before next tile's prologue

        // epilogue: HSH = fp16( (acc + bias) * dis[row] )
#pragma unroll
        for (int ti = 0; ti < 4; ti++) {
            int row0 = bR * 128 + wm + ti * 16 + r;
            int row1 = row0 + 8;
            float dis0 = (row0 < NN) ? g_DIS[row0] : 0.f;
            float dis1 = (row1 < NN) ? g_DIS[row1] : 0.f;
#pragma unroll
            for (int tj = 0; tj < 4; tj++) {
                int col = bC * 128 + wn + tj * 8 + 2 * c;
                float bx = __ldg(bias + col), by = __ldg(bias + col + 1);
                if (row0 < NN) {
                    __half2 h = __floats2half2_rn((acc[ti][tj][0] + bx) * dis0,
                                                  (acc[ti][tj][1] + by) * dis0);
                    *(__half2*)(g_HSH + row0 * DD + col) = h;
                }
                if (row1 < NN) {
                    __half2 h = __floats2half2_rn((acc[ti][tj][2] + bx) * dis1,
                                                  (acc[ti][tj][3] + by) * dis1);
                    *(__half2*)(g_HSH + row1 * DD + col) = h;
                }
            }
        }
    }
}

// ---------------- aggregation: warp per node, fp16 rows (512B) ----------------
template <int LAYER1>
__global__ void __launch_bounds__(256) k_agg() {
    int w = (blockIdx.x * blockDim.x + threadIdx.x) >> 5;
    int lane = threadIdx.x & 31;
    if (w >= NN) return;
    int s = g_ROWPTR[w], e = g_ROWPTR[w + 1];
    const uint4* HS = (const uint4*)g_HSH;
    float acc[8];
#pragma unroll
    for (int q = 0; q < 8; q++) acc[q] = 0.f;

    for (int base = s; base < e; base += 32) {
        int cnt = e - base; if (cnt > 32) cnt = 32;
        int mysrc = (lane < cnt) ? g_CSRC[base + lane] : 0;
#pragma unroll 4
        for (int i = 0; i < cnt; i++) {
            int src = __shfl_sync(0xffffffffu, mysrc, i);
            uint4 v = __ldg(HS + src * 32 + lane);
            float2 f0 = __half22float2(*(__half2*)&v.x);
            float2 f1 = __half22float2(*(__half2*)&v.y);
            float2 f2 = __half22float2(*(__half2*)&v.z);
            float2 f3 = __half22float2(*(__half2*)&v.w);
            acc[0] += f0.x; acc[1] += f0.y;
            acc[2] += f1.x; acc[3] += f1.y;
            acc[4] += f2.x; acc[5] += f2.y;
            acc[6] += f3.x; acc[7] += f3.y;
        }
    }
    uint4 sv = __ldg(HS + w * 32 + lane);
    float2 s0 = __half22float2(*(__half2*)&sv.x);
    float2 s1 = __half22float2(*(__half2*)&sv.y);
    float2 s2 = __half22float2(*(__half2*)&sv.z);
    float2 s3 = __half22float2(*(__half2*)&sv.w);
    float dis = g_DIS[w];
    float o[8];
    o[0] = fmaxf(dis * (acc[0] + s0.x), 0.f);
    o[1] = fmaxf(dis * (acc[1] + s0.y), 0.f);
    o[2] = fmaxf(dis * (acc[2] + s1.x), 0.f);
    o[3] = fmaxf(dis * (acc[3] + s1.y), 0.f);
    o[4] = fmaxf(dis * (acc[4] + s2.x), 0.f);
    o[5] = fmaxf(dis * (acc[5] + s2.y), 0.f);
    o[6] = fmaxf(dis * (acc[6] + s3.x), 0.f);
    o[7] = fmaxf(dis * (acc[7] + s3.y), 0.f);
    if (LAYER1) {
        union { uint4 u; __half2 h2[4]; } pk;
        pk.h2[0] = __floats2half2_rn(o[0], o[1]);
        pk.h2[1] = __floats2half2_rn(o[2], o[3]);
        pk.h2[2] = __floats2half2_rn(o[4], o[5]);
        pk.h2[3] = __floats2half2_rn(o[6], o[7]);
        ((uint4*)g_XH)[w * 32 + lane] = pk.u;
    } else {
        float4* OUT4 = (float4*)g_U;
        OUT4[w * 64 + lane * 2 + 0] = make_float4(o[0], o[1], o[2], o[3]);
        OUT4[w * 64 + lane * 2 + 1] = make_float4(o[4], o[5], o[6], o[7]);
    }
}

// pool pass 1: 8 node-chunks per graph -> partial sums
__global__ void k_pool1() {
    int g = blockIdx.x, ch = blockIdx.y;
    int lane = threadIdx.x;
    int s = g_GSTART[g], e = g_GSTART[g + 1];
    int len = e - s;
    int c0 = s + (int)(((long long)len * ch) >> 3);
    int c1 = s + (int)(((long long)len * (ch + 1)) >> 3);
    const float4* U4 = (const float4*)g_U;
    float4 acc = make_float4(0.f, 0.f, 0.f, 0.f);
    for (int n = c0; n < c1; n++) {
        float4 v = __ldg(U4 + n * 64 + lane);
        acc.x += v.x; acc.y += v.y; acc.z += v.z; acc.w += v.w;
    }
    ((float4*)g_PART)[(ch * NG + g) * 64 + lane] = acc;
}

__global__ void k_pool2(float* __restrict__ out) {
    int g = blockIdx.x;
    int lane = threadIdx.x;
    const float4* P4 = (const float4*)g_PART;
    float4 acc = make_float4(0.f, 0.f, 0.f, 0.f);
#pragma unroll
    for (int ch = 0; ch < 8; ch++) {
        float4 v = P4[(ch * NG + g) * 64 + lane];
        acc.x += v.x; acc.y += v.y; acc.z += v.z; acc.w += v.w;
    }
    ((float4*)out)[g * 64 + lane] = acc;
}

// ---------------- launch ------------------------------------------------------

extern "C" void kernel_launch(void* const* d_in, const int* in_sizes, int n_in,
                              void* d_out, int out_size) {
    const int *seq = nullptr, *edge = nullptr, *batch = nullptr;
    const float *emb = nullptr, *W0 = nullptr, *b0 = nullptr, *W1 = nullptr, *b1 = nullptr;
    for (int i = 0; i < n_in; i++) {
        int s = in_sizes[i];
        if (s == NN * 16)            seq  = (const int*)d_in[i];
        else if (s == 2 * NE)        edge = (const int*)d_in[i];
        else if (s == NN)            batch = (const int*)d_in[i];
        else if (s == VOCAB * DD)    emb  = (const float*)d_in[i];
        else if (s == DD * DD) { if (!W0) W0 = (const float*)d_in[i]; else W1 = (const float*)d_in[i]; }
        else if (s == DD)      { if (!b0) b0 = (const float*)d_in[i]; else b1 = (const float*)d_in[i]; }
    }
    float* out = (float*)d_out;

    __half* w0t; cudaGetSymbolAddress((void**)&w0t, g_W0T);
    __half* w1t; cudaGetSymbolAddress((void**)&w1t, g_W1T);

    k_prep<<<VB + SB + TB, 256>>>(batch, emb, W0, W1);
    k_embed_count<<<WB + CB, 256>>>(seq, edge);
    k_scan<<<SB, 256>>>();

    // layer 1: persistent GEMM with W0 resident + CSR fill inside
    k_gemm_p<1><<<PG, 256>>>(w0t, b0, edge);
    k_agg<1><<<WB, 256>>>();
    // layer 2: persistent GEMM with W1 resident
    k_gemm_p<0><<<PG, 256>>>(w1t, b1, nullptr);
    k_agg<0><<<WB, 256>>>();
    // pool
    dim3 pg(NG, 8);
    k_pool1<<<pg, 64>>>();
    k_pool2<<<NG, 64>>>(out);
}